// round 12
// baseline (speedup 1.0000x reference)
#include <cuda_runtime.h>
#include <cuda_bf16.h>
#include <cstdint>

// Shapes (fixed by the problem): B=8, N=2048, low=512, high=4096
#define Bb 8
#define Nn 2048
#define LO 512
#define HI 4096
#define BIGF 9.0e15f

// ---------------- fp32 scratch --------------------------------------------
__device__ float g_E[Bb*LO*HI];        // raw scores; later reused as fp32 Rt
__device__ float g_s[Bb*LO];
__device__ float g_u[Bb*LO];
__device__ float g_v[Bb*HI];
__device__ float g_w[Bb*HI];
__device__ float g_z[Bb*HI];

// ---------------- bf16 hi/lo operands (K-major) -----------------------------
__device__ __align__(256) __nv_bfloat16 g_XtH[Bb*LO*Nn];
__device__ __align__(256) __nv_bfloat16 g_XtL[Bb*LO*Nn];
__device__ __align__(256) __nv_bfloat16 g_WqH[LO*LO];
__device__ __align__(256) __nv_bfloat16 g_WqL[LO*LO];
__device__ __align__(256) __nv_bfloat16 g_WkH[HI*LO];
__device__ __align__(256) __nv_bfloat16 g_WkL[HI*LO];
__device__ __align__(256) __nv_bfloat16 g_WvTH[LO*LO];
__device__ __align__(256) __nv_bfloat16 g_WvTL[LO*LO];
__device__ __align__(256) __nv_bfloat16 g_GH [Bb*LO*LO];
__device__ __align__(256) __nv_bfloat16 g_GL [Bb*LO*LO];
__device__ __align__(256) __nv_bfloat16 g_TH [Bb*LO*LO];
__device__ __align__(256) __nv_bfloat16 g_TL [Bb*LO*LO];
__device__ __align__(256) __nv_bfloat16 g_SH [Bb*HI*LO];
__device__ __align__(256) __nv_bfloat16 g_SL [Bb*HI*LO];

// ---------------- int8 2-level operands + row scales ------------------------
__device__ __align__(256) signed char g_oq1[HI*HI];
__device__ __align__(256) signed char g_oq2[HI*HI];
__device__ float g_oSc[HI];
__device__ __align__(256) signed char g_aq1[Bb*LO*HI];
__device__ __align__(256) signed char g_aq2[Bb*LO*HI];
__device__ float g_aSc[Bb*LO];
__device__ __align__(256) signed char g_xq1[Bb*Nn*LO];
__device__ __align__(256) signed char g_xq2[Bb*Nn*LO];
__device__ float g_xSc[Bb*Nn];
__device__ __align__(256) signed char g_rq1[Bb*HI*LO];
__device__ __align__(256) signed char g_rq2[Bb*HI*LO];
__device__ float g_rSc[Bb*HI];

// ---------------- PTX helpers ----------------------------------------------
__device__ __forceinline__ uint32_t s2u(const void* p) {
    uint32_t a;
    asm("{ .reg .u64 t; cvta.to.shared.u64 t, %1; cvt.u32.u64 %0, t; }" : "=r"(a) : "l"(p));
    return a;
}
#define SWZ(x) ((x) ^ (((x) >> 3) & 0x70))

__device__ __forceinline__ void cp16(uint32_t sa, const void* ga) {
    asm volatile("cp.async.cg.shared.global [%0], [%1], 16;" :: "r"(sa), "l"(ga));
}

__device__ __forceinline__ void ldsm4(uint32_t& r0, uint32_t& r1, uint32_t& r2,
                                      uint32_t& r3, uint32_t a) {
    asm volatile("ldmatrix.sync.aligned.m8n8.x4.shared.b16 {%0,%1,%2,%3}, [%4];"
        : "=r"(r0), "=r"(r1), "=r"(r2), "=r"(r3) : "r"(a));
}

__device__ __forceinline__ void mma16816(float* d, const uint32_t* a,
                                         uint32_t b0, uint32_t b1) {
    asm volatile(
        "mma.sync.aligned.m16n8k16.row.col.f32.bf16.bf16.f32 "
        "{%0,%1,%2,%3}, {%4,%5,%6,%7}, {%8,%9}, {%0,%1,%2,%3};"
        : "+f"(d[0]), "+f"(d[1]), "+f"(d[2]), "+f"(d[3])
        : "r"(a[0]), "r"(a[1]), "r"(a[2]), "r"(a[3]), "r"(b0), "r"(b1));
}

__device__ __forceinline__ void imma16832(int* d, const uint32_t* a,
                                          uint32_t b0, uint32_t b1) {
    asm volatile(
        "mma.sync.aligned.m16n8k32.row.col.s32.s8.s8.s32 "
        "{%0,%1,%2,%3}, {%4,%5,%6,%7}, {%8,%9}, {%0,%1,%2,%3};"
        : "+r"(d[0]), "+r"(d[1]), "+r"(d[2]), "+r"(d[3])
        : "r"(a[0]), "r"(a[1]), "r"(a[2]), "r"(a[3]), "r"(b0), "r"(b1));
}

__device__ __forceinline__ __nv_bfloat162 split_pair(float x, float y, __nv_bfloat162& lo) {
    __nv_bfloat16 hx = __float2bfloat16(x);
    __nv_bfloat16 hy = __float2bfloat16(y);
    __nv_bfloat16 lx = __float2bfloat16(x - __bfloat162float(hx));
    __nv_bfloat16 ly = __float2bfloat16(y - __bfloat162float(hy));
    lo = __nv_bfloat162(lx, ly);
    return __nv_bfloat162(hx, hy);
}

// ============================================================================
// bf16 engine: C = Ah·Bh^T + Al·Bh^T + Ah·Bl^T   (proven R8/R9 code)
// CTA 128x128, 256 thr, K-chunk 64, 3-stage cp.async.
// ============================================================================
#define STAGES 3
#define KCH 64
#define STAGE_T 16384
#define STAGE_BYTES 65536
#define GEMM_SMEM (STAGES * STAGE_BYTES)   // 196608

__global__ void __launch_bounds__(256) mma_gemm(
    int K,
    const __nv_bfloat16* __restrict__ Ahi, const __nv_bfloat16* __restrict__ Alo, long sA,
    const __nv_bfloat16* __restrict__ Bhi, const __nv_bfloat16* __restrict__ Blo, long sB,
    float* __restrict__ C,
    __nv_bfloat16* __restrict__ Chi, __nv_bfloat16* __restrict__ Clo,
    int ldc, long sC,
    const float* __restrict__ bias, long sBias)
{
    extern __shared__ char smem[];
    const uint32_t sb = s2u(smem);
    const int tid = threadIdx.x;
    const int wid = tid >> 5, lane = tid & 31;
    const int bz = blockIdx.z;
    const int row0 = blockIdx.y * 128;
    const int col0 = blockIdx.x * 128;
    Ahi += (long)bz * sA; Alo += (long)bz * sA;
    Bhi += (long)bz * sB; Blo += (long)bz * sB;

    const int warp_m = (wid & 3) * 32;
    const int warp_n = (wid >> 2) * 64;

    float acc[2][8][4];
#pragma unroll
    for (int mi = 0; mi < 2; mi++)
#pragma unroll
        for (int ni = 0; ni < 8; ni++)
#pragma unroll
            for (int q = 0; q < 4; q++) acc[mi][ni][q] = 0.f;

    const int NC = K / KCH;

    auto load_chunk = [&](int c, int s) {
        uint32_t st = sb + s * STAGE_BYTES;
        long k0 = (long)c * KCH;
#pragma unroll
        for (int i = 0; i < 16; i++) {
            int idx = tid + i * 256;
            int t = i >> 2;
            int j = idx & 1023;
            int r = j >> 3, cj = j & 7;
            const __nv_bfloat16* src = (t == 0) ? Ahi : (t == 1) ? Alo
                                     : (t == 2) ? Bhi : Blo;
            int rb = (t < 2) ? row0 : col0;
            cp16(st + t * STAGE_T + SWZ(r * 128 + cj * 16),
                 src + (long)(rb + r) * K + k0 + cj * 8);
        }
    };

    const int lrow = lane & 15;
    const int lcol = (lane >> 4) * 16;

    load_chunk(0, 0);
    asm volatile("cp.async.commit_group;" ::: "memory");
    if (NC > 1) load_chunk(1, 1);
    asm volatile("cp.async.commit_group;" ::: "memory");

    for (int c = 0; c < NC; c++) {
        asm volatile("cp.async.wait_group 1;" ::: "memory");
        __syncthreads();
        if (c + 2 < NC) load_chunk(c + 2, (c + 2) % STAGES);
        asm volatile("cp.async.commit_group;" ::: "memory");

        uint32_t st = sb + (c % STAGES) * STAGE_BYTES;
        uint32_t ahb = st, alb = st + STAGE_T;
        uint32_t bhb = st + 2 * STAGE_T, blb = st + 3 * STAGE_T;
#pragma unroll
        for (int ks = 0; ks < 4; ks++) {
            uint32_t afh[2][4], afl[2][4], bfh[8][2], bfl[8][2];
#pragma unroll
            for (int mi = 0; mi < 2; mi++) {
                uint32_t off = SWZ((warp_m + mi * 16 + lrow) * 128 + ks * 32 + lcol);
                ldsm4(afh[mi][0], afh[mi][1], afh[mi][2], afh[mi][3], ahb + off);
                ldsm4(afl[mi][0], afl[mi][1], afl[mi][2], afl[mi][3], alb + off);
            }
#pragma unroll
            for (int nb = 0; nb < 4; nb++) {
                uint32_t off = SWZ((warp_n + nb * 16 + lrow) * 128 + ks * 32 + lcol);
                uint32_t r0, r1, r2, r3;
                ldsm4(r0, r1, r2, r3, bhb + off);
                bfh[2 * nb][0] = r0; bfh[2 * nb][1] = r2;
                bfh[2 * nb + 1][0] = r1; bfh[2 * nb + 1][1] = r3;
                ldsm4(r0, r1, r2, r3, blb + off);
                bfl[2 * nb][0] = r0; bfl[2 * nb][1] = r2;
                bfl[2 * nb + 1][0] = r1; bfl[2 * nb + 1][1] = r3;
            }
#pragma unroll
            for (int mi = 0; mi < 2; mi++)
#pragma unroll
                for (int ni = 0; ni < 8; ni++)
                    mma16816(acc[mi][ni], afh[mi], bfh[ni][0], bfh[ni][1]);
#pragma unroll
            for (int mi = 0; mi < 2; mi++)
#pragma unroll
                for (int ni = 0; ni < 8; ni++)
                    mma16816(acc[mi][ni], afl[mi], bfh[ni][0], bfh[ni][1]);
#pragma unroll
            for (int mi = 0; mi < 2; mi++)
#pragma unroll
                for (int ni = 0; ni < 8; ni++)
                    mma16816(acc[mi][ni], afh[mi], bfl[ni][0], bfl[ni][1]);
        }
    }

    const int cbase = col0 + warp_n + (lane & 3) * 2;
#pragma unroll
    for (int mi = 0; mi < 2; mi++) {
#pragma unroll
        for (int h = 0; h < 2; h++) {
            int row = row0 + warp_m + mi * 16 + (lane >> 2) + h * 8;
            long base = (long)bz * sC + (long)row * ldc + cbase;
            if (C) {
                float* cr = C + base;
                if (bias) {
                    const float* bp = bias + bz * sBias + cbase;
#pragma unroll
                    for (int ni = 0; ni < 8; ni++) {
                        float2 v;
                        v.x = acc[mi][ni][h * 2]     + bp[ni * 8];
                        v.y = acc[mi][ni][h * 2 + 1] + bp[ni * 8 + 1];
                        *(float2*)(cr + ni * 8) = v;
                    }
                } else {
#pragma unroll
                    for (int ni = 0; ni < 8; ni++) {
                        float2 v;
                        v.x = acc[mi][ni][h * 2];
                        v.y = acc[mi][ni][h * 2 + 1];
                        *(float2*)(cr + ni * 8) = v;
                    }
                }
            }
            if (Chi) {
#pragma unroll
                for (int ni = 0; ni < 8; ni++) {
                    __nv_bfloat162 lo;
                    __nv_bfloat162 hi = split_pair(acc[mi][ni][h * 2],
                                                   acc[mi][ni][h * 2 + 1], lo);
                    *(__nv_bfloat162*)(Chi + base + ni * 8) = hi;
                    *(__nv_bfloat162*)(Clo + base + ni * 8) = lo;
                }
            }
        }
    }
}

// ============================================================================
// int8 engine: C = sA[m]·sB[n]·(P11 + (P12+P21)/256 + P22/65536)
// Exact 2-level ladder products. CTA 128x128, 256 thr, K-chunk 128, 3 stages.
// 4 K-segments time-multiplexed in one launch; fp32 running acc, flushed per
// segment (int32 partials exact, |P| <= K·127^2 < 2^31).
// ============================================================================
#define IKCH 128
#define IST_T 16384
#define IST_BYTES 32768
#define IMMA_SMEM (3 * IST_BYTES)   // 98304

__global__ void __launch_bounds__(256) imma_gemm(
    int K,
    const signed char* __restrict__ Aq1, const signed char* __restrict__ Aq2,
    const float* __restrict__ sAv, long strA, long strSA,
    const signed char* __restrict__ Bq1, const signed char* __restrict__ Bq2,
    const float* __restrict__ sBv, long strB, long strSB,
    float* __restrict__ C,
    __nv_bfloat16* __restrict__ Chi, __nv_bfloat16* __restrict__ Clo,
    int ldc, long sC,
    const float* __restrict__ bias, long sBias)
{
    extern __shared__ char smem[];
    const uint32_t sb = s2u(smem);
    const int tid = threadIdx.x;
    const int wid = tid >> 5, lane = tid & 31;
    const int bz = blockIdx.z;
    const int row0 = blockIdx.y * 128;
    const int col0 = blockIdx.x * 128;
    Aq1 += (long)bz * strA; Aq2 += (long)bz * strA;
    Bq1 += (long)bz * strB; Bq2 += (long)bz * strB;

    const int warp_m = (wid & 3) * 32;
    const int warp_n = (wid >> 2) * 64;

    float accf[2][8][4];
    int   acci[2][8][4];
#pragma unroll
    for (int mi = 0; mi < 2; mi++)
#pragma unroll
        for (int ni = 0; ni < 8; ni++)
#pragma unroll
            for (int q = 0; q < 4; q++) { accf[mi][ni][q] = 0.f; acci[mi][ni][q] = 0; }

    const int NCK = K / IKCH;
    const int NC4 = 4 * NCK;

    auto load_chunk = [&](int g, int s) {
        int seg = g / NCK;
        const signed char* Ap = (seg < 2) ? Aq1 : Aq2;
        const signed char* Bp = (seg & 1) ? Bq2 : Bq1;
        long k0 = (long)(g - seg * NCK) * IKCH;
        uint32_t st = sb + s * IST_BYTES;
#pragma unroll
        for (int i = 0; i < 8; i++) {
            int idx = tid + i * 256;
            int j = idx & 1023;
            int r = j >> 3, cj = j & 7;
            const signed char* src = (idx < 1024) ? Ap : Bp;
            int rb = (idx < 1024) ? row0 : col0;
            uint32_t base = (idx < 1024) ? st : (st + IST_T);
            cp16(base + SWZ(r * 128 + cj * 16),
                 src + (long)(rb + r) * K + k0 + cj * 16);
        }
    };

    const int lrow = lane & 15;
    const int lcol = (lane >> 4) * 16;

    load_chunk(0, 0);
    asm volatile("cp.async.commit_group;" ::: "memory");
    load_chunk(1, 1);
    asm volatile("cp.async.commit_group;" ::: "memory");

    for (int c = 0; c < NC4; c++) {
        asm volatile("cp.async.wait_group 1;" ::: "memory");
        __syncthreads();
        if (c + 2 < NC4) load_chunk(c + 2, (c + 2) % 3);
        asm volatile("cp.async.commit_group;" ::: "memory");

        uint32_t st = sb + (c % 3) * IST_BYTES;
        uint32_t ab = st, bb = st + IST_T;
#pragma unroll
        for (int ks = 0; ks < 4; ks++) {
            uint32_t af[2][4], bf[8][2];
#pragma unroll
            for (int mi = 0; mi < 2; mi++) {
                uint32_t off = SWZ((warp_m + mi * 16 + lrow) * 128 + ks * 32 + lcol);
                ldsm4(af[mi][0], af[mi][1], af[mi][2], af[mi][3], ab + off);
            }
#pragma unroll
            for (int ng = 0; ng < 4; ng++) {
                uint32_t off = SWZ((warp_n + ng * 16 + lrow) * 128 + ks * 32 + lcol);
                uint32_t r0, r1, r2, r3;
                ldsm4(r0, r1, r2, r3, bb + off);
                bf[2 * ng][0] = r0; bf[2 * ng][1] = r2;
                bf[2 * ng + 1][0] = r1; bf[2 * ng + 1][1] = r3;
            }
#pragma unroll
            for (int mi = 0; mi < 2; mi++)
#pragma unroll
                for (int ni = 0; ni < 8; ni++)
                    imma16832(acci[mi][ni], af[mi], bf[ni][0], bf[ni][1]);
        }

        int seg = c / NCK;
        if (c == NC4 - 1 || (c + 1) / NCK != seg) {
            float w = (seg == 0) ? 1.0f : (seg == 3) ? (1.0f/65536.0f) : (1.0f/256.0f);
#pragma unroll
            for (int mi = 0; mi < 2; mi++)
#pragma unroll
                for (int ni = 0; ni < 8; ni++)
#pragma unroll
                    for (int q = 0; q < 4; q++) {
                        accf[mi][ni][q] += w * (float)acci[mi][ni][q];
                        acci[mi][ni][q] = 0;
                    }
        }
    }

    // epilogue with row/col scales
    const int cbase = col0 + warp_n + (lane & 3) * 2;
    float sb_c[16];
#pragma unroll
    for (int ni = 0; ni < 8; ni++) {
        sb_c[2 * ni]     = sBv[bz * strSB + cbase + ni * 8];
        sb_c[2 * ni + 1] = sBv[bz * strSB + cbase + ni * 8 + 1];
    }
#pragma unroll
    for (int mi = 0; mi < 2; mi++) {
#pragma unroll
        for (int h = 0; h < 2; h++) {
            int row = row0 + warp_m + mi * 16 + (lane >> 2) + h * 8;
            float sa = sAv[bz * strSA + row];
            long base = (long)bz * sC + (long)row * ldc + cbase;
            if (C) {
                float* cr = C + base;
                if (bias) {
                    const float* bp = bias + bz * sBias + cbase;
#pragma unroll
                    for (int ni = 0; ni < 8; ni++) {
                        float2 v;
                        v.x = sa * sb_c[2*ni]   * accf[mi][ni][h * 2]     + bp[ni * 8];
                        v.y = sa * sb_c[2*ni+1] * accf[mi][ni][h * 2 + 1] + bp[ni * 8 + 1];
                        *(float2*)(cr + ni * 8) = v;
                    }
                } else {
#pragma unroll
                    for (int ni = 0; ni < 8; ni++) {
                        float2 v;
                        v.x = sa * sb_c[2*ni]   * accf[mi][ni][h * 2];
                        v.y = sa * sb_c[2*ni+1] * accf[mi][ni][h * 2 + 1];
                        *(float2*)(cr + ni * 8) = v;
                    }
                }
            }
            if (Chi) {
#pragma unroll
                for (int ni = 0; ni < 8; ni++) {
                    __nv_bfloat162 lo;
                    __nv_bfloat162 hi = split_pair(sa * sb_c[2*ni]   * accf[mi][ni][h * 2],
                                                   sa * sb_c[2*ni+1] * accf[mi][ni][h * 2 + 1], lo);
                    *(__nv_bfloat162*)(Chi + base + ni * 8) = hi;
                    *(__nv_bfloat162*)(Clo + base + ni * 8) = lo;
                }
            }
        }
    }
}

// ---------------- fp32 -> int8 2-level rowwise quantization -----------------
__global__ void rowquant_kernel(const float* __restrict__ src, long sS,
                                signed char* __restrict__ q1,
                                signed char* __restrict__ q2,
                                float* __restrict__ scale,
                                long sQ, long sSc, int K)
{
    __shared__ float red[8];
    int row = blockIdx.x, b = blockIdx.y;
    const float* s = src + (long)b * sS + (long)row * K;
    signed char* p1 = q1 + (long)b * sQ + (long)row * K;
    signed char* p2 = q2 + (long)b * sQ + (long)row * K;
    int tid = threadIdx.x, wid = tid >> 5, lane = tid & 31;

    float m = 0.f;
    for (int k = tid; k < K; k += 256) m = fmaxf(m, fabsf(s[k]));
#pragma unroll
    for (int o = 16; o; o >>= 1) m = fmaxf(m, __shfl_xor_sync(0xffffffffu, m, o));
    if (lane == 0) red[wid] = m;
    __syncthreads();
    m = red[0];
#pragma unroll
    for (int i = 1; i < 8; i++) m = fmaxf(m, red[i]);

    float sc  = (m > 0.f) ? m / 127.f : 1.f;
    float inv = (m > 0.f) ? 127.f / m : 0.f;
    if (tid == 0) scale[(long)b * sSc + row] = sc;

    for (int k = tid; k < K; k += 256) {
        float x = s[k];
        int a1 = __float2int_rn(x * inv);
        float r = x - sc * (float)a1;
        int a2 = __float2int_rn(r * inv * 256.f);
        a2 = max(-128, min(127, a2));
        p1[k] = (signed char)a1;
        p2[k] = (signed char)a2;
    }
}

// ---------------- fp32 -> bf16 hi/lo split (coalesced) ----------------------
__global__ void split2_kernel(const float* __restrict__ src, long sS,
                              __nv_bfloat16* __restrict__ hi,
                              __nv_bfloat16* __restrict__ lo,
                              long sD, int pairs)
{
    int b = blockIdx.y;
    const float2* s2 = (const float2*)(src + (long)b * sS);
    __nv_bfloat162* h2 = (__nv_bfloat162*)(hi + (long)b * sD);
    __nv_bfloat162* l2 = (__nv_bfloat162*)(lo + (long)b * sD);
    for (int i = blockIdx.x * 256 + threadIdx.x; i < pairs; i += gridDim.x * 256) {
        float2 x = s2[i];
        __nv_bfloat162 lv;
        __nv_bfloat162 hv = split_pair(x.x, x.y, lv);
        h2[i] = hv;
        l2[i] = lv;
    }
}

// transpose + split: src [R,C] -> hi/lo [C,R]
__global__ void tsplit2_kernel(const float* __restrict__ src, long sS,
                               __nv_bfloat16* __restrict__ hi,
                               __nv_bfloat16* __restrict__ lo,
                               long sD, int R, int C)
{
    __shared__ float t[32][33];
    int b = blockIdx.z;
    src += (long)b * sS;
    int r0 = blockIdx.y * 32, c0 = blockIdx.x * 32;
    int tx = threadIdx.x, ty = threadIdx.y;   // (32, 8)
#pragma unroll
    for (int i = 0; i < 4; i++)
        t[ty + 8 * i][tx] = src[(long)(r0 + ty + 8 * i) * C + c0 + tx];
    __syncthreads();
#pragma unroll
    for (int i = 0; i < 4; i++) {
        int cc = c0 + ty + 8 * i;
        int rr = r0 + tx;
        float x = t[tx][ty + 8 * i];
        __nv_bfloat16 h = __float2bfloat16(x);
        __nv_bfloat16 l = __float2bfloat16(x - __bfloat162float(h));
        long o = (long)b * sD + (long)cc * R + rr;
        hi[o] = h;
        lo[o] = l;
    }
}

// ---------------- small helper kernels --------------------------------------
__device__ __forceinline__ float warpSum(float v) {
#pragma unroll
    for (int o = 16; o; o >>= 1) v += __shfl_xor_sync(0xffffffffu, v, o);
    return v;
}

__global__ void colsum_kernel(const float* __restrict__ X, float* __restrict__ s) {
    int b = blockIdx.x, m = threadIdx.x;
    const float* xb = X + (long)b * Nn * LO;
    float acc = 0.f;
    for (int n = 0; n < Nn; n++) acc += xb[(long)n * LO + m];
    s[b * LO + m] = acc;
}

__global__ void rowdot_kernel(const float* __restrict__ W, const float* __restrict__ x,
                              float* __restrict__ out, int rows, int cols,
                              const float* __restrict__ addv) {
    int warp = threadIdx.x >> 5, lane = threadIdx.x & 31;
    int r = blockIdx.x * 8 + warp;
    int b = blockIdx.y;
    if (r >= rows) return;
    const float* xb = x + (long)b * cols;
    const float* wr = W + (long)r * cols;
    float s = 0.f;
    for (int c = lane; c < cols; c += 32) s += wr[c] * xb[c];
    s = warpSum(s);
    if (lane == 0) out[(long)b * rows + r] = s + (addv ? addv[r] : 0.f);
}

// w[b][h] = sum_l bv[l] * dequant(A[b,l,h])
__global__ void wvec_kernel(const signed char* __restrict__ aq1,
                            const signed char* __restrict__ aq2,
                            const float* __restrict__ aSc,
                            const float* __restrict__ bv,
                            float* __restrict__ w) {
    int h = blockIdx.x * 256 + threadIdx.x;
    int b = blockIdx.y;
    const signed char* q1 = aq1 + (long)b * LO * HI;
    const signed char* q2 = aq2 + (long)b * LO * HI;
    float acc = 0.f;
    for (int l = 0; l < LO; l++) {
        long o = (long)l * HI + h;
        float a = aSc[b * LO + l] * ((float)q1[o] + (float)q2[o] * (1.f/256.f));
        acc += bv[l] * a;
    }
    w[(long)b * HI + h] = acc;
}

// ---------------- fused softmax + min-max-norm attention combine ------------
// reads raw scores E, writes attn weights as int8 2-level + row scale
__global__ void __launch_bounds__(256) attn_kernel(
    const float* __restrict__ E, const int* __restrict__ linkage,
    const float* __restrict__ u, const float* __restrict__ bq,
    const float* __restrict__ v, const float* __restrict__ bk,
    signed char* __restrict__ aq1, signed char* __restrict__ aq2,
    float* __restrict__ aSc)
{
    __shared__ float red[8];
    const int l = blockIdx.x, b = blockIdx.y;
    const float* row = E + ((long)(b * LO + l)) * HI;
    const int* lrow = linkage + (long)l * HI;
    const float* vb = v + (long)b * HI;
    const float uval = u[b * LO + l];
    const float bqv  = bq[l];

    float ev[16];
    unsigned mbits = 0;
    float gmax = -3.4e38f, mn = BIGF, mx = -BIGF;

#pragma unroll
    for (int j = 0; j < 16; j++) {
        int hh = threadIdx.x + j * 256;
        float bkh = bk[hh];
        float e = (row[hh] + uval * bkh + bqv * (vb[hh] + (float)Nn * bkh)) * 0.015625f;
        ev[j] = e;
        gmax = fmaxf(gmax, e);
        if (lrow[hh] > 0) {
            mbits |= 1u << j;
            mn = fminf(mn, e);
            mx = fmaxf(mx, e);
        }
    }

    const int wid = threadIdx.x >> 5, lane = threadIdx.x & 31;
#pragma unroll
    for (int o = 16; o; o >>= 1) gmax = fmaxf(gmax, __shfl_xor_sync(0xffffffffu, gmax, o));
    if (lane == 0) red[wid] = gmax;
    __syncthreads();
    gmax = red[0];
#pragma unroll
    for (int i = 1; i < 8; i++) gmax = fmaxf(gmax, red[i]);
    __syncthreads();

#pragma unroll
    for (int o = 16; o; o >>= 1) mn = fminf(mn, __shfl_xor_sync(0xffffffffu, mn, o));
    if (lane == 0) red[wid] = mn;
    __syncthreads();
    mn = red[0];
#pragma unroll
    for (int i = 1; i < 8; i++) mn = fminf(mn, red[i]);
    __syncthreads();

#pragma unroll
    for (int o = 16; o; o >>= 1) mx = fmaxf(mx, __shfl_xor_sync(0xffffffffu, mx, o));
    if (lane == 0) red[wid] = mx;
    __syncthreads();
    mx = red[0];
#pragma unroll
    for (int i = 1; i < 8; i++) mx = fmaxf(mx, red[i]);
    __syncthreads();

    float den = mx - mn;
    if (den == 0.0f) den = 1e-6f;
    const bool hasMask = (mx != -BIGF);
    const float lmax = hasMask ? (((mx - mn) == 0.0f) ? 0.0f : 1.0f) : -BIGF;

    float eg[16], el[16];
    float gsum = 0.f, lsum = 0.f;
#pragma unroll
    for (int j = 0; j < 16; j++) {
        float e = ev[j];
        float g = __expf(e - gmax);
        eg[j] = g;
        gsum += g;
        float lv = ((mbits >> j) & 1) ? (e - mn) / den : -BIGF;
        float ll = __expf(lv - lmax);
        el[j] = ll;
        lsum += ll;
    }

    gsum = warpSum(gsum);
    if (lane == 0) red[wid] = gsum;
    __syncthreads();
    gsum = red[0];
#pragma unroll
    for (int i = 1; i < 8; i++) gsum += red[i];
    __syncthreads();

    lsum = warpSum(lsum);
    if (lane == 0) red[wid] = lsum;
    __syncthreads();
    lsum = red[0];
#pragma unroll
    for (int i = 1; i < 8; i++) lsum += red[i];
    __syncthreads();

    const float rg = 1.0f / gsum, rl = 1.0f / lsum;
    float av[16];
    float amax = 0.f;
#pragma unroll
    for (int j = 0; j < 16; j++) {
        av[j] = eg[j] * rg + el[j] * rl;
        amax = fmaxf(amax, av[j]);
    }
#pragma unroll
    for (int o = 16; o; o >>= 1) amax = fmaxf(amax, __shfl_xor_sync(0xffffffffu, amax, o));
    if (lane == 0) red[wid] = amax;
    __syncthreads();
    amax = red[0];
#pragma unroll
    for (int i = 1; i < 8; i++) amax = fmaxf(amax, red[i]);

    float sc  = (amax > 0.f) ? amax / 127.f : 1.f;
    float inv = (amax > 0.f) ? 127.f / amax : 0.f;
    if (threadIdx.x == 0) aSc[b * LO + l] = sc;

    long obase = ((long)(b * LO + l)) * HI;
#pragma unroll
    for (int j = 0; j < 16; j++) {
        int hh = threadIdx.x + j * 256;
        float a = av[j];
        int a1 = __float2int_rn(a * inv);
        float r = a - sc * (float)a1;
        int a2 = __float2int_rn(r * inv * 256.f);
        a2 = max(-128, min(127, a2));
        aq1[obase + hh] = (signed char)a1;
        aq2[obase + hh] = (signed char)a2;
    }
}

// ---------------- host launch ------------------------------------------------
template <typename T>
static T* symaddr(const void* sym) {
    void* p = nullptr;
    cudaGetSymbolAddress(&p, sym);
    return (T*)p;
}

extern "C" void kernel_launch(void* const* d_in, const int* in_sizes, int n_in,
                              void* d_out, int out_size) {
    const float* X   = (const float*)d_in[0];
    const int*   lk  = (const int*)d_in[1];
    const float* wq  = (const float*)d_in[2];
    const float* bq  = (const float*)d_in[3];
    const float* wk  = (const float*)d_in[4];
    const float* bk  = (const float*)d_in[5];
    const float* wv  = (const float*)d_in[6];
    const float* bv  = (const float*)d_in[7];
    const float* ow  = (const float*)d_in[8];
    const float* ob  = (const float*)d_in[9];
    float* out = (float*)d_out;

    float* E = symaddr<float>(g_E);
    float* s = symaddr<float>(g_s);
    float* u = symaddr<float>(g_u);
    float* v = symaddr<float>(g_v);
    float* w = symaddr<float>(g_w);
    float* z = symaddr<float>(g_z);

    __nv_bfloat16* XtH  = symaddr<__nv_bfloat16>(g_XtH);
    __nv_bfloat16* XtL  = symaddr<__nv_bfloat16>(g_XtL);
    __nv_bfloat16* WqH  = symaddr<__nv_bfloat16>(g_WqH);
    __nv_bfloat16* WqL  = symaddr<__nv_bfloat16>(g_WqL);
    __nv_bfloat16* WkH  = symaddr<__nv_bfloat16>(g_WkH);
    __nv_bfloat16* WkL  = symaddr<__nv_bfloat16>(g_WkL);
    __nv_bfloat16* WvTH = symaddr<__nv_bfloat16>(g_WvTH);
    __nv_bfloat16* WvTL = symaddr<__nv_bfloat16>(g_WvTL);
    __nv_bfloat16* GH   = symaddr<__nv_bfloat16>(g_GH);
    __nv_bfloat16* GL   = symaddr<__nv_bfloat16>(g_GL);
    __nv_bfloat16* TH   = symaddr<__nv_bfloat16>(g_TH);
    __nv_bfloat16* TL   = symaddr<__nv_bfloat16>(g_TL);
    __nv_bfloat16* SH   = symaddr<__nv_bfloat16>(g_SH);
    __nv_bfloat16* SL   = symaddr<__nv_bfloat16>(g_SL);

    signed char* oq1 = symaddr<signed char>(g_oq1);
    signed char* oq2 = symaddr<signed char>(g_oq2);
    float*       oSc = symaddr<float>(g_oSc);
    signed char* aq1 = symaddr<signed char>(g_aq1);
    signed char* aq2 = symaddr<signed char>(g_aq2);
    float*       aSc = symaddr<float>(g_aSc);
    signed char* xq1 = symaddr<signed char>(g_xq1);
    signed char* xq2 = symaddr<signed char>(g_xq2);
    float*       xSc = symaddr<float>(g_xSc);
    signed char* rq1 = symaddr<signed char>(g_rq1);
    signed char* rq2 = symaddr<signed char>(g_rq2);
    float*       rSc = symaddr<float>(g_rSc);

    cudaFuncSetAttribute(mma_gemm, cudaFuncAttributeMaxDynamicSharedMemorySize, GEMM_SMEM);
    cudaFuncSetAttribute(imma_gemm, cudaFuncAttributeMaxDynamicSharedMemorySize, IMMA_SMEM);

    dim3 tb(32, 8);

    // conversions / quantization (one-time)
    tsplit2_kernel<<<dim3(LO/32, Nn/32, Bb), tb>>>(X, (long)Nn*LO, XtH, XtL, (long)LO*Nn, Nn, LO);
    rowquant_kernel<<<dim3(Nn, Bb), 256>>>(X, (long)Nn*LO, xq1, xq2, xSc, (long)Nn*LO, Nn, LO);
    split2_kernel<<<dim3(512, 1), 256>>>(wq, 0, WqH, WqL, 0, LO*LO/2);
    split2_kernel<<<dim3(4096, 1), 256>>>(wk, 0, WkH, WkL, 0, HI*LO/2);
    tsplit2_kernel<<<dim3(LO/32, LO/32, 1), tb>>>(wv, 0, WvTH, WvTL, 0, LO, LO);
    rowquant_kernel<<<dim3(HI, 1), 256>>>(ow, 0, oq1, oq2, oSc, 0, 0, HI);

    // bias correction vectors (exact; zero-valued in this dataset)
    colsum_kernel<<<Bb, LO>>>(X, s);
    rowdot_kernel<<<dim3(LO/8, Bb), 256>>>(wq, s, u, LO, LO, nullptr);
    rowdot_kernel<<<dim3(HI/8, Bb), 256>>>(wk, s, v, HI, LO, nullptr);

    // G_b = Xt Xt^T   [512,512] K=2048  (bf16)
    mma_gemm<<<dim3(LO/128, LO/128, Bb), 256, GEMM_SMEM>>>(
        Nn, XtH, XtL, (long)LO*Nn, XtH, XtL, (long)LO*Nn,
        nullptr, GH, GL, LO, (long)LO*LO, nullptr, 0);

    // T_b = Wq G_b    (bf16)
    mma_gemm<<<dim3(LO/128, LO/128, Bb), 256, GEMM_SMEM>>>(
        LO, WqH, WqL, 0, GH, GL, (long)LO*LO,
        nullptr, TH, TL, LO, (long)LO*LO, nullptr, 0);

    // E_b = T_b Wk^T  [512,4096] K=512  (bf16, fp32 out)
    mma_gemm<<<dim3(HI/128, LO/128, Bb), 256, GEMM_SMEM>>>(
        LO, TH, TL, (long)LO*LO, WkH, WkL, 0,
        E, nullptr, nullptr, HI, (long)LO*HI, nullptr, 0);

    // A_b = softmax(e) + softmax(minmaxnorm(e, mask)) -> int8 2-level + scale
    attn_kernel<<<dim3(LO, Bb), 256>>>(E, lk, u, bq, v, bk, aq1, aq2, aSc);

    // bias path: w_b = bv^T A_b ; z_b = w_b O^T + o_b
    wvec_kernel<<<dim3(HI/256, Bb), 256>>>(aq1, aq2, aSc, bv, w);
    rowdot_kernel<<<dim3(HI/8, Bb), 256>>>(ow, w, z, HI, HI, ob);

    // S_b = O A_b^T   [4096,512] K=4096 (dominant, int8 engine) -> bf16 split
    imma_gemm<<<dim3(LO/128, HI/128, Bb), 256, IMMA_SMEM>>>(
        HI, oq1, oq2, oSc, 0, 0,
        aq1, aq2, aSc, (long)LO*HI, LO,
        nullptr, SH, SL, LO, (long)HI*LO, nullptr, 0);

    // Rt_b = S_b Wv   [4096,512] K=512  (bf16, fp32 out into reused g_E)
    mma_gemm<<<dim3(LO/128, HI/128, Bb), 256, GEMM_SMEM>>>(
        LO, SH, SL, (long)HI*LO, WvTH, WvTL, 0,
        E, nullptr, nullptr, LO, (long)HI*LO, nullptr, 0);

    // quantize Rt rows [HI, LO]
    rowquant_kernel<<<dim3(HI, Bb), 256>>>(E, (long)HI*LO, rq1, rq2, rSc, (long)HI*LO, HI, LO);

    // out_b = X_b R_b + z_b  [2048,4096] K=512 (int8 engine)
    imma_gemm<<<dim3(HI/128, Nn/128, Bb), 256, IMMA_SMEM>>>(
        LO, xq1, xq2, xSc, (long)Nn*LO, Nn,
        rq1, rq2, rSc, (long)HI*LO, HI,
        out, nullptr, nullptr, HI, (long)Nn*HI, z, HI);

    (void)in_sizes; (void)n_in; (void)out_size;
}

// round 14
// speedup vs baseline: 2.9105x; 2.9105x over previous
#include <cuda_runtime.h>
#include <cuda_bf16.h>
#include <cstdint>

// Shapes (fixed by the problem): B=8, N=2048, low=512, high=4096
#define Bb 8
#define Nn 2048
#define LO 512
#define HI 4096
#define BIGF 9.0e15f

// ---------------- fp32 scratch --------------------------------------------
__device__ float g_E[Bb*LO*HI];        // raw scores e' (pre-bias/scale)
__device__ float g_s[Bb*LO];
__device__ float g_u[Bb*LO];
__device__ float g_v[Bb*HI];
__device__ float g_w[Bb*HI];
__device__ float g_z[Bb*HI];

// ---------------- bf16 hi/lo operands (K-major) -----------------------------
__device__ __align__(256) __nv_bfloat16 g_XtH[Bb*LO*Nn];   // X^T per batch
__device__ __align__(256) __nv_bfloat16 g_XtL[Bb*LO*Nn];
__device__ __align__(256) __nv_bfloat16 g_XH [Bb*Nn*LO];   // X
__device__ __align__(256) __nv_bfloat16 g_XL [Bb*Nn*LO];
__device__ __align__(256) __nv_bfloat16 g_WqH[LO*LO];
__device__ __align__(256) __nv_bfloat16 g_WqL[LO*LO];
__device__ __align__(256) __nv_bfloat16 g_WkH[HI*LO];
__device__ __align__(256) __nv_bfloat16 g_WkL[HI*LO];
__device__ __align__(256) __nv_bfloat16 g_WvTH[LO*LO];     // Wv^T
__device__ __align__(256) __nv_bfloat16 g_WvTL[LO*LO];
__device__ __align__(256) __nv_bfloat16 g_OH [HI*HI];      // O
__device__ __align__(256) __nv_bfloat16 g_OL [HI*HI];
__device__ __align__(256) __nv_bfloat16 g_GH [Bb*LO*LO];   // X^T X (epilogue split)
__device__ __align__(256) __nv_bfloat16 g_GL [Bb*LO*LO];
__device__ __align__(256) __nv_bfloat16 g_TH [Bb*LO*LO];   // Wq G
__device__ __align__(256) __nv_bfloat16 g_TL [Bb*LO*LO];
__device__ __align__(256) __nv_bfloat16 g_AH [Bb*LO*HI];   // attn weights
__device__ __align__(256) __nv_bfloat16 g_AL [Bb*LO*HI];
__device__ __align__(256) __nv_bfloat16 g_SH [Bb*HI*LO];   // S = O A^T
__device__ __align__(256) __nv_bfloat16 g_SL [Bb*HI*LO];
__device__ __align__(256) __nv_bfloat16 g_RtH[Bb*HI*LO];   // R^T = S Wv
__device__ __align__(256) __nv_bfloat16 g_RtL[Bb*HI*LO];

// ---------------- PTX helpers ----------------------------------------------
__device__ __forceinline__ uint32_t s2u(const void* p) {
    uint32_t a;
    asm("{ .reg .u64 t; cvta.to.shared.u64 t, %1; cvt.u32.u64 %0, t; }" : "=r"(a) : "l"(p));
    return a;
}
// SW64 swizzle for 64-byte rows (conflict-free for ldmatrix + cp.async)
#define SWZ64(x) ((x) ^ (((x) >> 3) & 0x30))

__device__ __forceinline__ void cp16(uint32_t sa, const void* ga) {
    asm volatile("cp.async.cg.shared.global [%0], [%1], 16;" :: "r"(sa), "l"(ga));
}

__device__ __forceinline__ void ldsm4(uint32_t& r0, uint32_t& r1, uint32_t& r2,
                                      uint32_t& r3, uint32_t a) {
    asm volatile("ldmatrix.sync.aligned.m8n8.x4.shared.b16 {%0,%1,%2,%3}, [%4];"
        : "=r"(r0), "=r"(r1), "=r"(r2), "=r"(r3) : "r"(a));
}

__device__ __forceinline__ void mma16816(float* d, const uint32_t* a,
                                         uint32_t b0, uint32_t b1) {
    asm volatile(
        "mma.sync.aligned.m16n8k16.row.col.f32.bf16.bf16.f32 "
        "{%0,%1,%2,%3}, {%4,%5,%6,%7}, {%8,%9}, {%0,%1,%2,%3};"
        : "+f"(d[0]), "+f"(d[1]), "+f"(d[2]), "+f"(d[3])
        : "r"(a[0]), "r"(a[1]), "r"(a[2]), "r"(a[3]), "r"(b0), "r"(b1));
}

__device__ __forceinline__ __nv_bfloat162 split_pair(float x, float y, __nv_bfloat162& lo) {
    __nv_bfloat16 hx = __float2bfloat16(x);
    __nv_bfloat16 hy = __float2bfloat16(y);
    __nv_bfloat16 lx = __float2bfloat16(x - __bfloat162float(hx));
    __nv_bfloat16 ly = __float2bfloat16(y - __bfloat162float(hy));
    lo = __nv_bfloat162(lx, ly);
    return __nv_bfloat162(hx, hy);
}

// ============================================================================
// bf16 engine: C = Ah·Bh^T + Al·Bh^T + Ah·Bl^T
// CTA 128x128, 256 thr, K-chunk 32 (64B rows, SW64), 3-stage cp.async.
// 96 KB smem/CTA -> 2 CTAs/SM (4 warps/SMSP) to cover barriers + latency.
// ============================================================================
#define KCH 32
#define STAGE_T 8192                   // one 128x32 bf16 tile (64 B rows)
#define STAGE_BYTES 32768              // Ahi + Alo + Bhi + Blo
#define GEMM_SMEM (3 * STAGE_BYTES)    // 98304 -> 2 CTAs/SM

__global__ void __launch_bounds__(256, 2) mma_gemm(
    int K,
    const __nv_bfloat16* __restrict__ Ahi, const __nv_bfloat16* __restrict__ Alo, long sA,
    const __nv_bfloat16* __restrict__ Bhi, const __nv_bfloat16* __restrict__ Blo, long sB,
    float* __restrict__ C,
    __nv_bfloat16* __restrict__ Chi, __nv_bfloat16* __restrict__ Clo,
    int ldc, long sC,
    const float* __restrict__ bias, long sBias)
{
    extern __shared__ char smem[];
    const uint32_t sb = s2u(smem);
    const int tid = threadIdx.x;
    const int wid = tid >> 5, lane = tid & 31;
    const int bz = blockIdx.z;
    const int row0 = blockIdx.y * 128;
    const int col0 = blockIdx.x * 128;
    Ahi += (long)bz * sA; Alo += (long)bz * sA;
    Bhi += (long)bz * sB; Blo += (long)bz * sB;

    const int warp_m = (wid & 3) * 32;
    const int warp_n = (wid >> 2) * 64;

    float acc[2][8][4];
#pragma unroll
    for (int mi = 0; mi < 2; mi++)
#pragma unroll
        for (int ni = 0; ni < 8; ni++)
#pragma unroll
            for (int q = 0; q < 4; q++) acc[mi][ni][q] = 0.f;

    const int NC = K / KCH;

    // 32 KB stage = 4 tiles x (128 rows x 64 B); 2048 x 16B chunks, 8/thread
    auto load_chunk = [&](int c, int s) {
        uint32_t st = sb + s * STAGE_BYTES;
        long k0 = (long)c * KCH;
#pragma unroll
        for (int i = 0; i < 8; i++) {
            int idx = tid + i * 256;
            int t = i >> 1;                  // tile 0..3 (compile-time)
            int j = idx & 511;
            int r = j >> 2, cj = j & 3;
            const __nv_bfloat16* src = (t == 0) ? Ahi : (t == 1) ? Alo
                                     : (t == 2) ? Bhi : Blo;
            int rb = (t < 2) ? row0 : col0;
            cp16(st + t * STAGE_T + SWZ64(r * 64 + cj * 16),
                 src + (long)(rb + r) * K + k0 + cj * 8);
        }
    };

    const int lrow = lane & 15;
    const int lcol = (lane >> 4) * 16;

    load_chunk(0, 0);
    asm volatile("cp.async.commit_group;" ::: "memory");
    load_chunk(1, 1);
    asm volatile("cp.async.commit_group;" ::: "memory");

    for (int c = 0; c < NC; c++) {
        asm volatile("cp.async.wait_group 1;" ::: "memory");
        __syncthreads();                     // chunk c ready; c-1 consumed
        if (c + 2 < NC) load_chunk(c + 2, (c + 2) % 3);
        asm volatile("cp.async.commit_group;" ::: "memory");

        uint32_t st = sb + (c % 3) * STAGE_BYTES;
        uint32_t ahb = st, alb = st + STAGE_T;
        uint32_t bhb = st + 2 * STAGE_T, blb = st + 3 * STAGE_T;
#pragma unroll
        for (int ks = 0; ks < 2; ks++) {
            uint32_t afh[2][4], afl[2][4];
#pragma unroll
            for (int mi = 0; mi < 2; mi++) {
                uint32_t off = SWZ64((warp_m + mi * 16 + lrow) * 64 + ks * 32 + lcol);
                ldsm4(afh[mi][0], afh[mi][1], afh[mi][2], afh[mi][3], ahb + off);
                ldsm4(afl[mi][0], afl[mi][1], afl[mi][2], afl[mi][3], alb + off);
            }
#pragma unroll
            for (int nb = 0; nb < 4; nb++) {
                uint32_t off = SWZ64((warp_n + nb * 16 + lrow) * 64 + ks * 32 + lcol);
                uint32_t h0, h1, h2, h3, l0, l1, l2, l3;
                ldsm4(h0, h1, h2, h3, bhb + off);
                ldsm4(l0, l1, l2, l3, blb + off);
#pragma unroll
                for (int mi = 0; mi < 2; mi++) {
                    mma16816(acc[mi][2 * nb],     afh[mi], h0, h2);
                    mma16816(acc[mi][2 * nb + 1], afh[mi], h1, h3);
                    mma16816(acc[mi][2 * nb],     afl[mi], h0, h2);
                    mma16816(acc[mi][2 * nb + 1], afl[mi], h1, h3);
                    mma16816(acc[mi][2 * nb],     afh[mi], l0, l2);
                    mma16816(acc[mi][2 * nb + 1], afh[mi], l1, l3);
                }
            }
        }
    }

    // epilogue: thread holds rows lane/4 (+8), col pairs (lane%4)*2
    const int cbase = col0 + warp_n + (lane & 3) * 2;
#pragma unroll
    for (int mi = 0; mi < 2; mi++) {
#pragma unroll
        for (int h = 0; h < 2; h++) {
            int row = row0 + warp_m + mi * 16 + (lane >> 2) + h * 8;
            long base = (long)bz * sC + (long)row * ldc + cbase;
            if (C) {
                float* cr = C + base;
                if (bias) {
                    const float* bp = bias + bz * sBias + cbase;
#pragma unroll
                    for (int ni = 0; ni < 8; ni++) {
                        float2 v;
                        v.x = acc[mi][ni][h * 2]     + bp[ni * 8];
                        v.y = acc[mi][ni][h * 2 + 1] + bp[ni * 8 + 1];
                        *(float2*)(cr + ni * 8) = v;
                    }
                } else {
#pragma unroll
                    for (int ni = 0; ni < 8; ni++) {
                        float2 v;
                        v.x = acc[mi][ni][h * 2];
                        v.y = acc[mi][ni][h * 2 + 1];
                        *(float2*)(cr + ni * 8) = v;
                    }
                }
            }
            if (Chi) {
#pragma unroll
                for (int ni = 0; ni < 8; ni++) {
                    __nv_bfloat162 lo;
                    __nv_bfloat162 hi = split_pair(acc[mi][ni][h * 2],
                                                   acc[mi][ni][h * 2 + 1], lo);
                    *(__nv_bfloat162*)(Chi + base + ni * 8) = hi;
                    *(__nv_bfloat162*)(Clo + base + ni * 8) = lo;
                }
            }
        }
    }
}

// ---------------- fp32 -> bf16 hi/lo split (coalesced) ----------------------
__global__ void split2_kernel(const float* __restrict__ src, long sS,
                              __nv_bfloat16* __restrict__ hi,
                              __nv_bfloat16* __restrict__ lo,
                              long sD, int pairs)
{
    int b = blockIdx.y;
    const float2* s2 = (const float2*)(src + (long)b * sS);
    __nv_bfloat162* h2 = (__nv_bfloat162*)(hi + (long)b * sD);
    __nv_bfloat162* l2 = (__nv_bfloat162*)(lo + (long)b * sD);
    for (int i = blockIdx.x * 256 + threadIdx.x; i < pairs; i += gridDim.x * 256) {
        float2 x = s2[i];
        __nv_bfloat162 lv;
        __nv_bfloat162 hv = split_pair(x.x, x.y, lv);
        h2[i] = hv;
        l2[i] = lv;
    }
}

// transpose + split: src [R,C] -> hi/lo [C,R]
__global__ void tsplit2_kernel(const float* __restrict__ src, long sS,
                               __nv_bfloat16* __restrict__ hi,
                               __nv_bfloat16* __restrict__ lo,
                               long sD, int R, int C)
{
    __shared__ float t[32][33];
    int b = blockIdx.z;
    src += (long)b * sS;
    int r0 = blockIdx.y * 32, c0 = blockIdx.x * 32;
    int tx = threadIdx.x, ty = threadIdx.y;   // (32, 8)
#pragma unroll
    for (int i = 0; i < 4; i++)
        t[ty + 8 * i][tx] = src[(long)(r0 + ty + 8 * i) * C + c0 + tx];
    __syncthreads();
#pragma unroll
    for (int i = 0; i < 4; i++) {
        int cc = c0 + ty + 8 * i;
        int rr = r0 + tx;
        float x = t[tx][ty + 8 * i];
        __nv_bfloat16 h = __float2bfloat16(x);
        __nv_bfloat16 l = __float2bfloat16(x - __bfloat162float(h));
        long o = (long)b * sD + (long)cc * R + rr;
        hi[o] = h;
        lo[o] = l;
    }
}

// ---------------- small helper kernels --------------------------------------
__device__ __forceinline__ float warpSum(float v) {
#pragma unroll
    for (int o = 16; o; o >>= 1) v += __shfl_xor_sync(0xffffffffu, v, o);
    return v;
}

__global__ void colsum_kernel(const float* __restrict__ X, float* __restrict__ s) {
    int b = blockIdx.x, m = threadIdx.x;
    const float* xb = X + (long)b * Nn * LO;
    float acc = 0.f;
    for (int n = 0; n < Nn; n++) acc += xb[(long)n * LO + m];
    s[b * LO + m] = acc;
}

__global__ void rowdot_kernel(const float* __restrict__ W, const float* __restrict__ x,
                              float* __restrict__ out, int rows, int cols,
                              const float* __restrict__ addv) {
    int warp = threadIdx.x >> 5, lane = threadIdx.x & 31;
    int r = blockIdx.x * 8 + warp;
    int b = blockIdx.y;
    if (r >= rows) return;
    const float* xb = x + (long)b * cols;
    const float* wr = W + (long)r * cols;
    float s = 0.f;
    for (int c = lane; c < cols; c += 32) s += wr[c] * xb[c];
    s = warpSum(s);
    if (lane == 0) out[(long)b * rows + r] = s + (addv ? addv[r] : 0.f);
}

// w[b][h] = sum_l bv[l] * (AH+AL)[b,l,h]
__global__ void wvec_kernel(const __nv_bfloat16* __restrict__ AH,
                            const __nv_bfloat16* __restrict__ AL,
                            const float* __restrict__ bv,
                            float* __restrict__ w) {
    int h = blockIdx.x * 256 + threadIdx.x;
    int b = blockIdx.y;
    const __nv_bfloat16* Ah = AH + (long)b * LO * HI;
    const __nv_bfloat16* Al = AL + (long)b * LO * HI;
    float acc = 0.f;
    for (int l = 0; l < LO; l++) {
        long o = (long)l * HI + h;
        acc += bv[l] * (__bfloat162float(Ah[o]) + __bfloat162float(Al[o]));
    }
    w[(long)b * HI + h] = acc;
}

// ---------------- fused softmax + min-max-norm attention combine ------------
__global__ void __launch_bounds__(256) attn_kernel(
    const float* __restrict__ E, const int* __restrict__ linkage,
    const float* __restrict__ u, const float* __restrict__ bq,
    const float* __restrict__ v, const float* __restrict__ bk,
    __nv_bfloat16* __restrict__ AH, __nv_bfloat16* __restrict__ AL)
{
    __shared__ float red[8];
    const int l = blockIdx.x, b = blockIdx.y;
    const float* row = E + ((long)(b * LO + l)) * HI;
    const int* lrow = linkage + (long)l * HI;
    const float* vb = v + (long)b * HI;
    const float uval = u[b * LO + l];
    const float bqv  = bq[l];

    float ev[16];
    unsigned mbits = 0;
    float gmax = -3.4e38f, mn = BIGF, mx = -BIGF;

#pragma unroll
    for (int j = 0; j < 16; j++) {
        int hh = threadIdx.x + j * 256;
        float bkh = bk[hh];
        float e = (row[hh] + uval * bkh + bqv * (vb[hh] + (float)Nn * bkh)) * 0.015625f;
        ev[j] = e;
        gmax = fmaxf(gmax, e);
        if (lrow[hh] > 0) {
            mbits |= 1u << j;
            mn = fminf(mn, e);
            mx = fmaxf(mx, e);
        }
    }

    const int wid = threadIdx.x >> 5, lane = threadIdx.x & 31;
#pragma unroll
    for (int o = 16; o; o >>= 1) gmax = fmaxf(gmax, __shfl_xor_sync(0xffffffffu, gmax, o));
    if (lane == 0) red[wid] = gmax;
    __syncthreads();
    gmax = red[0];
#pragma unroll
    for (int i = 1; i < 8; i++) gmax = fmaxf(gmax, red[i]);
    __syncthreads();

#pragma unroll
    for (int o = 16; o; o >>= 1) mn = fminf(mn, __shfl_xor_sync(0xffffffffu, mn, o));
    if (lane == 0) red[wid] = mn;
    __syncthreads();
    mn = red[0];
#pragma unroll
    for (int i = 1; i < 8; i++) mn = fminf(mn, red[i]);
    __syncthreads();

#pragma unroll
    for (int o = 16; o; o >>= 1) mx = fmaxf(mx, __shfl_xor_sync(0xffffffffu, mx, o));
    if (lane == 0) red[wid] = mx;
    __syncthreads();
    mx = red[0];
#pragma unroll
    for (int i = 1; i < 8; i++) mx = fmaxf(mx, red[i]);
    __syncthreads();

    float den = mx - mn;
    if (den == 0.0f) den = 1e-6f;
    const bool hasMask = (mx != -BIGF);
    const float lmax = hasMask ? (((mx - mn) == 0.0f) ? 0.0f : 1.0f) : -BIGF;

    float eg[16], el[16];
    float gsum = 0.f, lsum = 0.f;
#pragma unroll
    for (int j = 0; j < 16; j++) {
        float e = ev[j];
        float g = __expf(e - gmax);
        eg[j] = g;
        gsum += g;
        float lv = ((mbits >> j) & 1) ? (e - mn) / den : -BIGF;
        float ll = __expf(lv - lmax);
        el[j] = ll;
        lsum += ll;
    }

    gsum = warpSum(gsum);
    if (lane == 0) red[wid] = gsum;
    __syncthreads();
    gsum = red[0];
#pragma unroll
    for (int i = 1; i < 8; i++) gsum += red[i];
    __syncthreads();

    lsum = warpSum(lsum);
    if (lane == 0) red[wid] = lsum;
    __syncthreads();
    lsum = red[0];
#pragma unroll
    for (int i = 1; i < 8; i++) lsum += red[i];

    const float rg = 1.0f / gsum, rl = 1.0f / lsum;
    long obase = ((long)(b * LO + l)) * HI;
#pragma unroll
    for (int j = 0; j < 16; j++) {
        int hh = threadIdx.x + j * 256;
        float a = eg[j] * rg + el[j] * rl;
        __nv_bfloat16 ah = __float2bfloat16(a);
        __nv_bfloat16 al = __float2bfloat16(a - __bfloat162float(ah));
        AH[obase + hh] = ah;
        AL[obase + hh] = al;
    }
}

// ---------------- host launch ------------------------------------------------
template <typename T>
static T* symaddr(const void* sym) {
    void* p = nullptr;
    cudaGetSymbolAddress(&p, sym);
    return (T*)p;
}

extern "C" void kernel_launch(void* const* d_in, const int* in_sizes, int n_in,
                              void* d_out, int out_size) {
    const float* X   = (const float*)d_in[0];
    const int*   lk  = (const int*)d_in[1];
    const float* wq  = (const float*)d_in[2];
    const float* bq  = (const float*)d_in[3];
    const float* wk  = (const float*)d_in[4];
    const float* bk  = (const float*)d_in[5];
    const float* wv  = (const float*)d_in[6];
    const float* bv  = (const float*)d_in[7];
    const float* ow  = (const float*)d_in[8];
    const float* ob  = (const float*)d_in[9];
    float* out = (float*)d_out;

    float* E = symaddr<float>(g_E);
    float* s = symaddr<float>(g_s);
    float* u = symaddr<float>(g_u);
    float* v = symaddr<float>(g_v);
    float* w = symaddr<float>(g_w);
    float* z = symaddr<float>(g_z);

    __nv_bfloat16* XtH  = symaddr<__nv_bfloat16>(g_XtH);
    __nv_bfloat16* XtL  = symaddr<__nv_bfloat16>(g_XtL);
    __nv_bfloat16* XH   = symaddr<__nv_bfloat16>(g_XH);
    __nv_bfloat16* XL   = symaddr<__nv_bfloat16>(g_XL);
    __nv_bfloat16* WqH  = symaddr<__nv_bfloat16>(g_WqH);
    __nv_bfloat16* WqL  = symaddr<__nv_bfloat16>(g_WqL);
    __nv_bfloat16* WkH  = symaddr<__nv_bfloat16>(g_WkH);
    __nv_bfloat16* WkL  = symaddr<__nv_bfloat16>(g_WkL);
    __nv_bfloat16* WvTH = symaddr<__nv_bfloat16>(g_WvTH);
    __nv_bfloat16* WvTL = symaddr<__nv_bfloat16>(g_WvTL);
    __nv_bfloat16* OH   = symaddr<__nv_bfloat16>(g_OH);
    __nv_bfloat16* OL   = symaddr<__nv_bfloat16>(g_OL);
    __nv_bfloat16* GH   = symaddr<__nv_bfloat16>(g_GH);
    __nv_bfloat16* GL   = symaddr<__nv_bfloat16>(g_GL);
    __nv_bfloat16* TH   = symaddr<__nv_bfloat16>(g_TH);
    __nv_bfloat16* TL   = symaddr<__nv_bfloat16>(g_TL);
    __nv_bfloat16* AH   = symaddr<__nv_bfloat16>(g_AH);
    __nv_bfloat16* AL   = symaddr<__nv_bfloat16>(g_AL);
    __nv_bfloat16* SH   = symaddr<__nv_bfloat16>(g_SH);
    __nv_bfloat16* SL   = symaddr<__nv_bfloat16>(g_SL);
    __nv_bfloat16* RtH  = symaddr<__nv_bfloat16>(g_RtH);
    __nv_bfloat16* RtL  = symaddr<__nv_bfloat16>(g_RtL);

    cudaFuncSetAttribute(mma_gemm, cudaFuncAttributeMaxDynamicSharedMemorySize, GEMM_SMEM);

    dim3 tb(32, 8);

    // input/weight conversions (one-time)
    tsplit2_kernel<<<dim3(LO/32, Nn/32, Bb), tb>>>(X, (long)Nn*LO, XtH, XtL, (long)LO*Nn, Nn, LO);
    split2_kernel<<<dim3(2048, Bb), 256>>>(X, (long)Nn*LO, XH, XL, (long)Nn*LO, Nn*LO/2);
    split2_kernel<<<dim3(512, 1), 256>>>(wq, 0, WqH, WqL, 0, LO*LO/2);
    split2_kernel<<<dim3(4096, 1), 256>>>(wk, 0, WkH, WkL, 0, HI*LO/2);
    tsplit2_kernel<<<dim3(LO/32, LO/32, 1), tb>>>(wv, 0, WvTH, WvTL, 0, LO, LO);
    split2_kernel<<<dim3(8192, 1), 256>>>(ow, 0, OH, OL, 0, HI*HI/2);

    // bias correction vectors (exact; zero-valued in this dataset)
    colsum_kernel<<<Bb, LO>>>(X, s);
    rowdot_kernel<<<dim3(LO/8, Bb), 256>>>(wq, s, u, LO, LO, nullptr);
    rowdot_kernel<<<dim3(HI/8, Bb), 256>>>(wk, s, v, HI, LO, nullptr);

    // G_b = Xt Xt^T   [512,512] K=2048  -> hi/lo split epilogue
    mma_gemm<<<dim3(LO/128, LO/128, Bb), 256, GEMM_SMEM>>>(
        Nn, XtH, XtL, (long)LO*Nn, XtH, XtL, (long)LO*Nn,
        nullptr, GH, GL, LO, (long)LO*LO, nullptr, 0);

    // T_b = Wq G_b    (G symmetric => rows of G are K-major)
    mma_gemm<<<dim3(LO/128, LO/128, Bb), 256, GEMM_SMEM>>>(
        LO, WqH, WqL, 0, GH, GL, (long)LO*LO,
        nullptr, TH, TL, LO, (long)LO*LO, nullptr, 0);

    // E_b = T_b Wk^T  [512,4096] K=512  -> fp32 (softmax needs it)
    mma_gemm<<<dim3(HI/128, LO/128, Bb), 256, GEMM_SMEM>>>(
        LO, TH, TL, (long)LO*LO, WkH, WkL, 0,
        E, nullptr, nullptr, HI, (long)LO*HI, nullptr, 0);

    // A_b = softmax(e) + softmax(minmaxnorm(e, mask)) -> hi/lo bf16
    attn_kernel<<<dim3(LO, Bb), 256>>>(E, lk, u, bq, v, bk, AH, AL);

    // bias path: w_b = bv^T A_b ; z_b = w_b O^T + o_b
    wvec_kernel<<<dim3(HI/256, Bb), 256>>>(AH, AL, bv, w);
    rowdot_kernel<<<dim3(HI/8, Bb), 256>>>(ow, w, z, HI, HI, ob);

    // S_b = O A_b^T   [4096,512] K=4096 (dominant) -> hi/lo split epilogue
    mma_gemm<<<dim3(LO/128, HI/128, Bb), 256, GEMM_SMEM>>>(
        HI, OH, OL, 0, AH, AL, (long)LO*HI,
        nullptr, SH, SL, LO, (long)HI*LO, nullptr, 0);

    // Rt_b = S_b Wv   [4096,512] K=512  (Bop = Wv^T)  -> hi/lo split epilogue
    mma_gemm<<<dim3(LO/128, HI/128, Bb), 256, GEMM_SMEM>>>(
        LO, SH, SL, (long)HI*LO, WvTH, WvTL, 0,
        nullptr, RtH, RtL, LO, (long)HI*LO, nullptr, 0);

    // out_b = X_b R_b + z_b  [2048,4096] K=512 (Bop = Rt rows)
    mma_gemm<<<dim3(HI/128, Nn/128, Bb), 256, GEMM_SMEM>>>(
        LO, XH, XL, (long)Nn*LO, RtH, RtL, (long)HI*LO,
        out, nullptr, nullptr, HI, (long)Nn*HI, z, HI);

    (void)in_sizes; (void)n_in; (void)out_size;
}

// round 15
// speedup vs baseline: 3.9247x; 1.3484x over previous
#include <cuda_runtime.h>
#include <cuda_bf16.h>
#include <cuda_fp16.h>
#include <cstdint>

// Shapes (fixed by the problem): B=8, N=2048, low=512, high=4096
#define Bb 8
#define Nn 2048
#define LO 512
#define HI 4096
#define BIGF 9.0e15f

// ---------------- fp32 scratch --------------------------------------------
__device__ float g_E[Bb*LO*HI];        // raw scores e' (pre-bias/scale)
__device__ float g_s[Bb*LO];
__device__ float g_u[Bb*LO];
__device__ float g_v[Bb*HI];
__device__ float g_w[Bb*HI];
__device__ float g_z[Bb*HI];

// ---------------- bf16 hi/lo operands (score chain, K-major) ----------------
__device__ __align__(256) __nv_bfloat16 g_XtH[Bb*LO*Nn];   // X^T per batch
__device__ __align__(256) __nv_bfloat16 g_XtL[Bb*LO*Nn];
__device__ __align__(256) __nv_bfloat16 g_WqH[LO*LO];
__device__ __align__(256) __nv_bfloat16 g_WqL[LO*LO];
__device__ __align__(256) __nv_bfloat16 g_WkH[HI*LO];
__device__ __align__(256) __nv_bfloat16 g_WkL[HI*LO];
__device__ __align__(256) __nv_bfloat16 g_GH [Bb*LO*LO];
__device__ __align__(256) __nv_bfloat16 g_GL [Bb*LO*LO];
__device__ __align__(256) __nv_bfloat16 g_TH [Bb*LO*LO];
__device__ __align__(256) __nv_bfloat16 g_TL [Bb*LO*LO];

// ---------------- fp16 operands (value chain, K-major) ----------------------
__device__ __align__(256) __half g_OhH[HI*HI];     // O hi
__device__ __align__(256) __half g_OhL[HI*HI];     // O lo
__device__ __align__(256) __half g_As [Bb*LO*HI];  // attn weights (single)
__device__ __align__(256) __half g_ShH[Bb*HI*LO];  // S = O A^T hi
__device__ __align__(256) __half g_ShL[Bb*HI*LO];  // S lo
__device__ __align__(256) __half g_WvTs[LO*LO];    // Wv^T (single)
__device__ __align__(256) __half g_Rts[Bb*HI*LO];  // R^T = S Wv (single)
__device__ __align__(256) __half g_XhH[Bb*Nn*LO];  // X hi
__device__ __align__(256) __half g_XhL[Bb*Nn*LO];  // X lo

// ---------------- PTX helpers ----------------------------------------------
__device__ __forceinline__ uint32_t s2u(const void* p) {
    uint32_t a;
    asm("{ .reg .u64 t; cvta.to.shared.u64 t, %1; cvt.u32.u64 %0, t; }" : "=r"(a) : "l"(p));
    return a;
}
// SW64 swizzle for 64-byte rows (conflict-free for ldmatrix + cp.async)
#define SWZ64(x) ((x) ^ (((x) >> 3) & 0x30))

__device__ __forceinline__ void cp16(uint32_t sa, const void* ga) {
    asm volatile("cp.async.cg.shared.global [%0], [%1], 16;" :: "r"(sa), "l"(ga));
}

__device__ __forceinline__ void ldsm4(uint32_t& r0, uint32_t& r1, uint32_t& r2,
                                      uint32_t& r3, uint32_t a) {
    asm volatile("ldmatrix.sync.aligned.m8n8.x4.shared.b16 {%0,%1,%2,%3}, [%4];"
        : "=r"(r0), "=r"(r1), "=r"(r2), "=r"(r3) : "r"(a));
}

__device__ __forceinline__ void mma16816(float* d, const uint32_t* a,
                                         uint32_t b0, uint32_t b1) {
    asm volatile(
        "mma.sync.aligned.m16n8k16.row.col.f32.bf16.bf16.f32 "
        "{%0,%1,%2,%3}, {%4,%5,%6,%7}, {%8,%9}, {%0,%1,%2,%3};"
        : "+f"(d[0]), "+f"(d[1]), "+f"(d[2]), "+f"(d[3])
        : "r"(a[0]), "r"(a[1]), "r"(a[2]), "r"(a[3]), "r"(b0), "r"(b1));
}

__device__ __forceinline__ void mma16816h(float* d, const uint32_t* a,
                                          uint32_t b0, uint32_t b1) {
    asm volatile(
        "mma.sync.aligned.m16n8k16.row.col.f32.f16.f16.f32 "
        "{%0,%1,%2,%3}, {%4,%5,%6,%7}, {%8,%9}, {%0,%1,%2,%3};"
        : "+f"(d[0]), "+f"(d[1]), "+f"(d[2]), "+f"(d[3])
        : "r"(a[0]), "r"(a[1]), "r"(a[2]), "r"(a[3]), "r"(b0), "r"(b1));
}

__device__ __forceinline__ __nv_bfloat162 split_pair(float x, float y, __nv_bfloat162& lo) {
    __nv_bfloat16 hx = __float2bfloat16(x);
    __nv_bfloat16 hy = __float2bfloat16(y);
    __nv_bfloat16 lx = __float2bfloat16(x - __bfloat162float(hx));
    __nv_bfloat16 ly = __float2bfloat16(y - __bfloat162float(hy));
    lo = __nv_bfloat162(lx, ly);
    return __nv_bfloat162(hx, hy);
}

__device__ __forceinline__ __half2 split_pair_h(float x, float y, __half2& lo) {
    __half hx = __float2half_rn(x), hy = __float2half_rn(y);
    __half lx = __float2half_rn(x - __half2float(hx));
    __half ly = __float2half_rn(y - __half2float(hy));
    lo = __halves2half2(lx, ly);
    return __halves2half2(hx, hy);
}

// ============================================================================
// bf16 engine (score chain): C = Ah·Bh^T + Al·Bh^T + Ah·Bl^T
// CTA 128x128, 256 thr, K-chunk 32 (64B rows, SW64), 3-stage, 2 CTAs/SM.
// ============================================================================
#define KCH 32
#define STAGE_T 8192
#define STAGE_BYTES 32768
#define GEMM_SMEM (3 * STAGE_BYTES)    // 98304

__global__ void __launch_bounds__(256, 2) mma_gemm(
    int K,
    const __nv_bfloat16* __restrict__ Ahi, const __nv_bfloat16* __restrict__ Alo, long sA,
    const __nv_bfloat16* __restrict__ Bhi, const __nv_bfloat16* __restrict__ Blo, long sB,
    float* __restrict__ C,
    __nv_bfloat16* __restrict__ Chi, __nv_bfloat16* __restrict__ Clo,
    int ldc, long sC)
{
    extern __shared__ char smem[];
    const uint32_t sb = s2u(smem);
    const int tid = threadIdx.x;
    const int wid = tid >> 5, lane = tid & 31;
    const int bz = blockIdx.z;
    const int row0 = blockIdx.y * 128;
    const int col0 = blockIdx.x * 128;
    Ahi += (long)bz * sA; Alo += (long)bz * sA;
    Bhi += (long)bz * sB; Blo += (long)bz * sB;

    const int warp_m = (wid & 3) * 32;
    const int warp_n = (wid >> 2) * 64;

    float acc[2][8][4];
#pragma unroll
    for (int mi = 0; mi < 2; mi++)
#pragma unroll
        for (int ni = 0; ni < 8; ni++)
#pragma unroll
            for (int q = 0; q < 4; q++) acc[mi][ni][q] = 0.f;

    const int NC = K / KCH;

    auto load_chunk = [&](int c, int s) {
        uint32_t st = sb + s * STAGE_BYTES;
        long k0 = (long)c * KCH;
#pragma unroll
        for (int i = 0; i < 8; i++) {
            int idx = tid + i * 256;
            int t = i >> 1;
            int j = idx & 511;
            int r = j >> 2, cj = j & 3;
            const __nv_bfloat16* src = (t == 0) ? Ahi : (t == 1) ? Alo
                                     : (t == 2) ? Bhi : Blo;
            int rb = (t < 2) ? row0 : col0;
            cp16(st + t * STAGE_T + SWZ64(r * 64 + cj * 16),
                 src + (long)(rb + r) * K + k0 + cj * 8);
        }
    };

    const int lrow = lane & 15;
    const int lcol = (lane >> 4) * 16;

    load_chunk(0, 0);
    asm volatile("cp.async.commit_group;" ::: "memory");
    load_chunk(1, 1);
    asm volatile("cp.async.commit_group;" ::: "memory");

    for (int c = 0; c < NC; c++) {
        asm volatile("cp.async.wait_group 1;" ::: "memory");
        __syncthreads();
        if (c + 2 < NC) load_chunk(c + 2, (c + 2) % 3);
        asm volatile("cp.async.commit_group;" ::: "memory");

        uint32_t st = sb + (c % 3) * STAGE_BYTES;
        uint32_t ahb = st, alb = st + STAGE_T;
        uint32_t bhb = st + 2 * STAGE_T, blb = st + 3 * STAGE_T;
#pragma unroll
        for (int ks = 0; ks < 2; ks++) {
            uint32_t afh[2][4], afl[2][4];
#pragma unroll
            for (int mi = 0; mi < 2; mi++) {
                uint32_t off = SWZ64((warp_m + mi * 16 + lrow) * 64 + ks * 32 + lcol);
                ldsm4(afh[mi][0], afh[mi][1], afh[mi][2], afh[mi][3], ahb + off);
                ldsm4(afl[mi][0], afl[mi][1], afl[mi][2], afl[mi][3], alb + off);
            }
#pragma unroll
            for (int nb = 0; nb < 4; nb++) {
                uint32_t off = SWZ64((warp_n + nb * 16 + lrow) * 64 + ks * 32 + lcol);
                uint32_t h0, h1, h2, h3, l0, l1, l2, l3;
                ldsm4(h0, h1, h2, h3, bhb + off);
                ldsm4(l0, l1, l2, l3, blb + off);
#pragma unroll
                for (int mi = 0; mi < 2; mi++) {
                    mma16816(acc[mi][2 * nb],     afh[mi], h0, h2);
                    mma16816(acc[mi][2 * nb + 1], afh[mi], h1, h3);
                    mma16816(acc[mi][2 * nb],     afl[mi], h0, h2);
                    mma16816(acc[mi][2 * nb + 1], afl[mi], h1, h3);
                    mma16816(acc[mi][2 * nb],     afh[mi], l0, l2);
                    mma16816(acc[mi][2 * nb + 1], afh[mi], l1, l3);
                }
            }
        }
    }

    const int cbase = col0 + warp_n + (lane & 3) * 2;
#pragma unroll
    for (int mi = 0; mi < 2; mi++) {
#pragma unroll
        for (int h = 0; h < 2; h++) {
            int row = row0 + warp_m + mi * 16 + (lane >> 2) + h * 8;
            long base = (long)bz * sC + (long)row * ldc + cbase;
            if (C) {
                float* cr = C + base;
#pragma unroll
                for (int ni = 0; ni < 8; ni++) {
                    float2 v;
                    v.x = acc[mi][ni][h * 2];
                    v.y = acc[mi][ni][h * 2 + 1];
                    *(float2*)(cr + ni * 8) = v;
                }
            }
            if (Chi) {
#pragma unroll
                for (int ni = 0; ni < 8; ni++) {
                    __nv_bfloat162 lo;
                    __nv_bfloat162 hi = split_pair(acc[mi][ni][h * 2],
                                                   acc[mi][ni][h * 2 + 1], lo);
                    *(__nv_bfloat162*)(Chi + base + ni * 8) = hi;
                    *(__nv_bfloat162*)(Clo + base + ni * 8) = lo;
                }
            }
        }
    }
}

// ============================================================================
// fp16 2-product engine (value chain): C = (Ah+Al)[M,K] · Bs[N,K]^T
// A hi/lo fp16, B single fp16. 2/3 the HMMA count of bf16x3.
// CTA 128x128, 256 thr, K-chunk 32, 3 tiles/stage (24 KB), 3 stages = 72 KB.
// ============================================================================
#define H2_STAGE_BYTES 24576
#define H2_SMEM (3 * H2_STAGE_BYTES)   // 73728

__global__ void __launch_bounds__(256, 2) mma_gemm_h2(
    int K,
    const __half* __restrict__ Ahi, const __half* __restrict__ Alo, long sA,
    const __half* __restrict__ Bs, long sB,
    float* __restrict__ C,
    __half* __restrict__ Chi, __half* __restrict__ Clo,
    __half* __restrict__ Cs,
    int ldc, long sC,
    const float* __restrict__ bias, long sBias)
{
    extern __shared__ char smem[];
    const uint32_t sb = s2u(smem);
    const int tid = threadIdx.x;
    const int wid = tid >> 5, lane = tid & 31;
    const int bz = blockIdx.z;
    const int row0 = blockIdx.y * 128;
    const int col0 = blockIdx.x * 128;
    Ahi += (long)bz * sA; Alo += (long)bz * sA;
    Bs  += (long)bz * sB;

    const int warp_m = (wid & 3) * 32;
    const int warp_n = (wid >> 2) * 64;

    float acc[2][8][4];
#pragma unroll
    for (int mi = 0; mi < 2; mi++)
#pragma unroll
        for (int ni = 0; ni < 8; ni++)
#pragma unroll
            for (int q = 0; q < 4; q++) acc[mi][ni][q] = 0.f;

    const int NC = K / KCH;

    // stage = 3 tiles x (128 rows x 64 B): Ahi @0, Alo @8192, B @16384
    auto load_chunk = [&](int c, int s) {
        uint32_t st = sb + s * H2_STAGE_BYTES;
        long k0 = (long)c * KCH;
#pragma unroll
        for (int i = 0; i < 6; i++) {
            int idx = tid + i * 256;
            int t = i >> 1;                  // 0=Ahi, 1=Alo, 2=B
            int j = idx & 511;
            int r = j >> 2, cj = j & 3;
            const __half* src = (t == 0) ? Ahi : (t == 1) ? Alo : Bs;
            int rb = (t < 2) ? row0 : col0;
            cp16(st + t * STAGE_T + SWZ64(r * 64 + cj * 16),
                 src + (long)(rb + r) * K + k0 + cj * 8);
        }
    };

    const int lrow = lane & 15;
    const int lcol = (lane >> 4) * 16;

    load_chunk(0, 0);
    asm volatile("cp.async.commit_group;" ::: "memory");
    load_chunk(1, 1);
    asm volatile("cp.async.commit_group;" ::: "memory");

    for (int c = 0; c < NC; c++) {
        asm volatile("cp.async.wait_group 1;" ::: "memory");
        __syncthreads();
        if (c + 2 < NC) load_chunk(c + 2, (c + 2) % 3);
        asm volatile("cp.async.commit_group;" ::: "memory");

        uint32_t st = sb + (c % 3) * H2_STAGE_BYTES;
        uint32_t ahb = st, alb = st + STAGE_T, bb = st + 2 * STAGE_T;
#pragma unroll
        for (int ks = 0; ks < 2; ks++) {
            uint32_t afh[2][4], afl[2][4];
#pragma unroll
            for (int mi = 0; mi < 2; mi++) {
                uint32_t off = SWZ64((warp_m + mi * 16 + lrow) * 64 + ks * 32 + lcol);
                ldsm4(afh[mi][0], afh[mi][1], afh[mi][2], afh[mi][3], ahb + off);
                ldsm4(afl[mi][0], afl[mi][1], afl[mi][2], afl[mi][3], alb + off);
            }
#pragma unroll
            for (int nb = 0; nb < 4; nb++) {
                uint32_t off = SWZ64((warp_n + nb * 16 + lrow) * 64 + ks * 32 + lcol);
                uint32_t b0, b1, b2, b3;
                ldsm4(b0, b1, b2, b3, bb + off);
#pragma unroll
                for (int mi = 0; mi < 2; mi++) {
                    mma16816h(acc[mi][2 * nb],     afh[mi], b0, b2);
                    mma16816h(acc[mi][2 * nb + 1], afh[mi], b1, b3);
                    mma16816h(acc[mi][2 * nb],     afl[mi], b0, b2);
                    mma16816h(acc[mi][2 * nb + 1], afl[mi], b1, b3);
                }
            }
        }
    }

    const int cbase = col0 + warp_n + (lane & 3) * 2;
#pragma unroll
    for (int mi = 0; mi < 2; mi++) {
#pragma unroll
        for (int h = 0; h < 2; h++) {
            int row = row0 + warp_m + mi * 16 + (lane >> 2) + h * 8;
            long base = (long)bz * sC + (long)row * ldc + cbase;
            if (C) {
                float* cr = C + base;
                if (bias) {
                    const float* bp = bias + bz * sBias + cbase;
#pragma unroll
                    for (int ni = 0; ni < 8; ni++) {
                        float2 v;
                        v.x = acc[mi][ni][h * 2]     + bp[ni * 8];
                        v.y = acc[mi][ni][h * 2 + 1] + bp[ni * 8 + 1];
                        *(float2*)(cr + ni * 8) = v;
                    }
                } else {
#pragma unroll
                    for (int ni = 0; ni < 8; ni++) {
                        float2 v;
                        v.x = acc[mi][ni][h * 2];
                        v.y = acc[mi][ni][h * 2 + 1];
                        *(float2*)(cr + ni * 8) = v;
                    }
                }
            }
            if (Chi) {
#pragma unroll
                for (int ni = 0; ni < 8; ni++) {
                    __half2 lo;
                    __half2 hi = split_pair_h(acc[mi][ni][h * 2],
                                              acc[mi][ni][h * 2 + 1], lo);
                    *(__half2*)(Chi + base + ni * 8) = hi;
                    *(__half2*)(Clo + base + ni * 8) = lo;
                }
            }
            if (Cs) {
#pragma unroll
                for (int ni = 0; ni < 8; ni++) {
                    __half2 v = __halves2half2(__float2half_rn(acc[mi][ni][h * 2]),
                                               __float2half_rn(acc[mi][ni][h * 2 + 1]));
                    *(__half2*)(Cs + base + ni * 8) = v;
                }
            }
        }
    }
}

// ---------------- fp32 -> bf16 hi/lo split (coalesced) ----------------------
__global__ void split2_kernel(const float* __restrict__ src, long sS,
                              __nv_bfloat16* __restrict__ hi,
                              __nv_bfloat16* __restrict__ lo,
                              long sD, int pairs)
{
    int b = blockIdx.y;
    const float2* s2 = (const float2*)(src + (long)b * sS);
    __nv_bfloat162* h2 = (__nv_bfloat162*)(hi + (long)b * sD);
    __nv_bfloat162* l2 = (__nv_bfloat162*)(lo + (long)b * sD);
    for (int i = blockIdx.x * 256 + threadIdx.x; i < pairs; i += gridDim.x * 256) {
        float2 x = s2[i];
        __nv_bfloat162 lv;
        __nv_bfloat162 hv = split_pair(x.x, x.y, lv);
        h2[i] = hv;
        l2[i] = lv;
    }
}

// ---------------- fp32 -> fp16 hi/lo split (coalesced) ----------------------
__global__ void splitH_kernel(const float* __restrict__ src, long sS,
                              __half* __restrict__ hi,
                              __half* __restrict__ lo,
                              long sD, int pairs)
{
    int b = blockIdx.y;
    const float2* s2 = (const float2*)(src + (long)b * sS);
    __half2* h2 = (__half2*)(hi + (long)b * sD);
    __half2* l2 = (__half2*)(lo + (long)b * sD);
    for (int i = blockIdx.x * 256 + threadIdx.x; i < pairs; i += gridDim.x * 256) {
        float2 x = s2[i];
        __half2 lv;
        __half2 hv = split_pair_h(x.x, x.y, lv);
        h2[i] = hv;
        l2[i] = lv;
    }
}

// transpose + split: src [R,C] -> hi/lo bf16 [C,R]
__global__ void tsplit2_kernel(const float* __restrict__ src, long sS,
                               __nv_bfloat16* __restrict__ hi,
                               __nv_bfloat16* __restrict__ lo,
                               long sD, int R, int C)
{
    __shared__ float t[32][33];
    int b = blockIdx.z;
    src += (long)b * sS;
    int r0 = blockIdx.y * 32, c0 = blockIdx.x * 32;
    int tx = threadIdx.x, ty = threadIdx.y;   // (32, 8)
#pragma unroll
    for (int i = 0; i < 4; i++)
        t[ty + 8 * i][tx] = src[(long)(r0 + ty + 8 * i) * C + c0 + tx];
    __syncthreads();
#pragma unroll
    for (int i = 0; i < 4; i++) {
        int cc = c0 + ty + 8 * i;
        int rr = r0 + tx;
        float x = t[tx][ty + 8 * i];
        __nv_bfloat16 h = __float2bfloat16(x);
        __nv_bfloat16 l = __float2bfloat16(x - __bfloat162float(h));
        long o = (long)b * sD + (long)cc * R + rr;
        hi[o] = h;
        lo[o] = l;
    }
}

// transpose: src [R,C] -> fp16 single [C,R]  (used for Wv^T only)
__global__ void tsplitH_kernel(const float* __restrict__ src,
                               __half* __restrict__ dst, int R, int C)
{
    __shared__ float t[32][33];
    int r0 = blockIdx.y * 32, c0 = blockIdx.x * 32;
    int tx = threadIdx.x, ty = threadIdx.y;   // (32, 8)
#pragma unroll
    for (int i = 0; i < 4; i++)
        t[ty + 8 * i][tx] = src[(long)(r0 + ty + 8 * i) * C + c0 + tx];
    __syncthreads();
#pragma unroll
    for (int i = 0; i < 4; i++) {
        int cc = c0 + ty + 8 * i;
        int rr = r0 + tx;
        dst[(long)cc * R + rr] = __float2half_rn(t[tx][ty + 8 * i]);
    }
}

// ---------------- small helper kernels --------------------------------------
__device__ __forceinline__ float warpSum(float v) {
#pragma unroll
    for (int o = 16; o; o >>= 1) v += __shfl_xor_sync(0xffffffffu, v, o);
    return v;
}

__global__ void colsum_kernel(const float* __restrict__ X, float* __restrict__ s) {
    int b = blockIdx.x, m = threadIdx.x;
    const float* xb = X + (long)b * Nn * LO;
    float acc = 0.f;
    for (int n = 0; n < Nn; n++) acc += xb[(long)n * LO + m];
    s[b * LO + m] = acc;
}

__global__ void rowdot_kernel(const float* __restrict__ W, const float* __restrict__ x,
                              float* __restrict__ out, int rows, int cols,
                              const float* __restrict__ addv) {
    int warp = threadIdx.x >> 5, lane = threadIdx.x & 31;
    int r = blockIdx.x * 8 + warp;
    int b = blockIdx.y;
    if (r >= rows) return;
    const float* xb = x + (long)b * cols;
    const float* wr = W + (long)r * cols;
    float s = 0.f;
    for (int c = lane; c < cols; c += 32) s += wr[c] * xb[c];
    s = warpSum(s);
    if (lane == 0) out[(long)b * rows + r] = s + (addv ? addv[r] : 0.f);
}

// w[b][h] = sum_l bv[l] * As[b,l,h]
__global__ void wvec_kernel(const __half* __restrict__ As,
                            const float* __restrict__ bv,
                            float* __restrict__ w) {
    int h = blockIdx.x * 256 + threadIdx.x;
    int b = blockIdx.y;
    const __half* Ab = As + (long)b * LO * HI;
    float acc = 0.f;
    for (int l = 0; l < LO; l++)
        acc += bv[l] * __half2float(Ab[(long)l * HI + h]);
    w[(long)b * HI + h] = acc;
}

// ---------------- fused softmax + min-max-norm attention combine ------------
// reads raw scores E, writes attn weights as single fp16
__global__ void __launch_bounds__(256) attn_kernel(
    const float* __restrict__ E, const int* __restrict__ linkage,
    const float* __restrict__ u, const float* __restrict__ bq,
    const float* __restrict__ v, const float* __restrict__ bk,
    __half* __restrict__ As)
{
    __shared__ float red[8];
    const int l = blockIdx.x, b = blockIdx.y;
    const float* row = E + ((long)(b * LO + l)) * HI;
    const int* lrow = linkage + (long)l * HI;
    const float* vb = v + (long)b * HI;
    const float uval = u[b * LO + l];
    const float bqv  = bq[l];

    float ev[16];
    unsigned mbits = 0;
    float gmax = -3.4e38f, mn = BIGF, mx = -BIGF;

#pragma unroll
    for (int j = 0; j < 16; j++) {
        int hh = threadIdx.x + j * 256;
        float bkh = bk[hh];
        float e = (row[hh] + uval * bkh + bqv * (vb[hh] + (float)Nn * bkh)) * 0.015625f;
        ev[j] = e;
        gmax = fmaxf(gmax, e);
        if (lrow[hh] > 0) {
            mbits |= 1u << j;
            mn = fminf(mn, e);
            mx = fmaxf(mx, e);
        }
    }

    const int wid = threadIdx.x >> 5, lane = threadIdx.x & 31;
#pragma unroll
    for (int o = 16; o; o >>= 1) gmax = fmaxf(gmax, __shfl_xor_sync(0xffffffffu, gmax, o));
    if (lane == 0) red[wid] = gmax;
    __syncthreads();
    gmax = red[0];
#pragma unroll
    for (int i = 1; i < 8; i++) gmax = fmaxf(gmax, red[i]);
    __syncthreads();

#pragma unroll
    for (int o = 16; o; o >>= 1) mn = fminf(mn, __shfl_xor_sync(0xffffffffu, mn, o));
    if (lane == 0) red[wid] = mn;
    __syncthreads();
    mn = red[0];
#pragma unroll
    for (int i = 1; i < 8; i++) mn = fminf(mn, red[i]);
    __syncthreads();

#pragma unroll
    for (int o = 16; o; o >>= 1) mx = fmaxf(mx, __shfl_xor_sync(0xffffffffu, mx, o));
    if (lane == 0) red[wid] = mx;
    __syncthreads();
    mx = red[0];
#pragma unroll
    for (int i = 1; i < 8; i++) mx = fmaxf(mx, red[i]);
    __syncthreads();

    float den = mx - mn;
    if (den == 0.0f) den = 1e-6f;
    const bool hasMask = (mx != -BIGF);
    const float lmax = hasMask ? (((mx - mn) == 0.0f) ? 0.0f : 1.0f) : -BIGF;

    float eg[16], el[16];
    float gsum = 0.f, lsum = 0.f;
#pragma unroll
    for (int j = 0; j < 16; j++) {
        float e = ev[j];
        float g = __expf(e - gmax);
        eg[j] = g;
        gsum += g;
        float lv = ((mbits >> j) & 1) ? (e - mn) / den : -BIGF;
        float ll = __expf(lv - lmax);
        el[j] = ll;
        lsum += ll;
    }

    gsum = warpSum(gsum);
    if (lane == 0) red[wid] = gsum;
    __syncthreads();
    gsum = red[0];
#pragma unroll
    for (int i = 1; i < 8; i++) gsum += red[i];
    __syncthreads();

    lsum = warpSum(lsum);
    if (lane == 0) red[wid] = lsum;
    __syncthreads();
    lsum = red[0];
#pragma unroll
    for (int i = 1; i < 8; i++) lsum += red[i];

    const float rg = 1.0f / gsum, rl = 1.0f / lsum;
    long obase = ((long)(b * LO + l)) * HI;
#pragma unroll
    for (int j = 0; j < 16; j++) {
        int hh = threadIdx.x + j * 256;
        As[obase + hh] = __float2half_rn(eg[j] * rg + el[j] * rl);
    }
}

// ---------------- host launch ------------------------------------------------
template <typename T>
static T* symaddr(const void* sym) {
    void* p = nullptr;
    cudaGetSymbolAddress(&p, sym);
    return (T*)p;
}

extern "C" void kernel_launch(void* const* d_in, const int* in_sizes, int n_in,
                              void* d_out, int out_size) {
    const float* X   = (const float*)d_in[0];
    const int*   lk  = (const int*)d_in[1];
    const float* wq  = (const float*)d_in[2];
    const float* bq  = (const float*)d_in[3];
    const float* wk  = (const float*)d_in[4];
    const float* bk  = (const float*)d_in[5];
    const float* wv  = (const float*)d_in[6];
    const float* bv  = (const float*)d_in[7];
    const float* ow  = (const float*)d_in[8];
    const float* ob  = (const float*)d_in[9];
    float* out = (float*)d_out;

    float* E = symaddr<float>(g_E);
    float* s = symaddr<float>(g_s);
    float* u = symaddr<float>(g_u);
    float* v = symaddr<float>(g_v);
    float* w = symaddr<float>(g_w);
    float* z = symaddr<float>(g_z);

    __nv_bfloat16* XtH = symaddr<__nv_bfloat16>(g_XtH);
    __nv_bfloat16* XtL = symaddr<__nv_bfloat16>(g_XtL);
    __nv_bfloat16* WqH = symaddr<__nv_bfloat16>(g_WqH);
    __nv_bfloat16* WqL = symaddr<__nv_bfloat16>(g_WqL);
    __nv_bfloat16* WkH = symaddr<__nv_bfloat16>(g_WkH);
    __nv_bfloat16* WkL = symaddr<__nv_bfloat16>(g_WkL);
    __nv_bfloat16* GH  = symaddr<__nv_bfloat16>(g_GH);
    __nv_bfloat16* GL  = symaddr<__nv_bfloat16>(g_GL);
    __nv_bfloat16* TH  = symaddr<__nv_bfloat16>(g_TH);
    __nv_bfloat16* TL  = symaddr<__nv_bfloat16>(g_TL);

    __half* OhH  = symaddr<__half>(g_OhH);
    __half* OhL  = symaddr<__half>(g_OhL);
    __half* As   = symaddr<__half>(g_As);
    __half* ShH  = symaddr<__half>(g_ShH);
    __half* ShL  = symaddr<__half>(g_ShL);
    __half* WvTs = symaddr<__half>(g_WvTs);
    __half* Rts  = symaddr<__half>(g_Rts);
    __half* XhH  = symaddr<__half>(g_XhH);
    __half* XhL  = symaddr<__half>(g_XhL);

    cudaFuncSetAttribute(mma_gemm, cudaFuncAttributeMaxDynamicSharedMemorySize, GEMM_SMEM);
    cudaFuncSetAttribute(mma_gemm_h2, cudaFuncAttributeMaxDynamicSharedMemorySize, H2_SMEM);

    dim3 tb(32, 8);

    // input/weight conversions (one-time)
    tsplit2_kernel<<<dim3(LO/32, Nn/32, Bb), tb>>>(X, (long)Nn*LO, XtH, XtL, (long)LO*Nn, Nn, LO);
    splitH_kernel<<<dim3(2048, Bb), 256>>>(X, (long)Nn*LO, XhH, XhL, (long)Nn*LO, Nn*LO/2);
    split2_kernel<<<dim3(512, 1), 256>>>(wq, 0, WqH, WqL, 0, LO*LO/2);
    split2_kernel<<<dim3(4096, 1), 256>>>(wk, 0, WkH, WkL, 0, HI*LO/2);
    tsplitH_kernel<<<dim3(LO/32, LO/32, 1), tb>>>(wv, WvTs, LO, LO);
    splitH_kernel<<<dim3(8192, 1), 256>>>(ow, 0, OhH, OhL, 0, HI*HI/2);

    // bias correction vectors (exact; zero-valued in this dataset)
    colsum_kernel<<<Bb, LO>>>(X, s);
    rowdot_kernel<<<dim3(LO/8, Bb), 256>>>(wq, s, u, LO, LO, nullptr);
    rowdot_kernel<<<dim3(HI/8, Bb), 256>>>(wk, s, v, HI, LO, nullptr);

    // -------- score chain (bf16x3) --------
    // G_b = Xt Xt^T   [512,512] K=2048  -> bf16 hi/lo split epilogue
    mma_gemm<<<dim3(LO/128, LO/128, Bb), 256, GEMM_SMEM>>>(
        Nn, XtH, XtL, (long)LO*Nn, XtH, XtL, (long)LO*Nn,
        nullptr, GH, GL, LO, (long)LO*LO);

    // T_b = Wq G_b
    mma_gemm<<<dim3(LO/128, LO/128, Bb), 256, GEMM_SMEM>>>(
        LO, WqH, WqL, 0, GH, GL, (long)LO*LO,
        nullptr, TH, TL, LO, (long)LO*LO);

    // E_b = T_b Wk^T  [512,4096] K=512  -> fp32
    mma_gemm<<<dim3(HI/128, LO/128, Bb), 256, GEMM_SMEM>>>(
        LO, TH, TL, (long)LO*LO, WkH, WkL, 0,
        E, nullptr, nullptr, HI, (long)LO*HI);

    // A_b = softmax(e) + softmax(minmaxnorm(e, mask)) -> single fp16
    attn_kernel<<<dim3(LO, Bb), 256>>>(E, lk, u, bq, v, bk, As);

    // bias path: w_b = bv^T A_b ; z_b = w_b O^T + o_b
    wvec_kernel<<<dim3(HI/256, Bb), 256>>>(As, bv, w);
    rowdot_kernel<<<dim3(HI/8, Bb), 256>>>(ow, w, z, HI, HI, ob);

    // -------- value chain (fp16 2-product) --------
    // S_b = O A_b^T   [4096,512] K=4096 (dominant) -> fp16 hi/lo epilogue
    mma_gemm_h2<<<dim3(LO/128, HI/128, Bb), 256, H2_SMEM>>>(
        HI, OhH, OhL, 0, As, (long)LO*HI,
        nullptr, ShH, ShL, nullptr, LO, (long)HI*LO, nullptr, 0);

    // Rt_b = S_b Wv   [4096,512] K=512  -> single fp16 epilogue
    mma_gemm_h2<<<dim3(LO/128, HI/128, Bb), 256, H2_SMEM>>>(
        LO, ShH, ShL, (long)HI*LO, WvTs, 0,
        nullptr, nullptr, nullptr, Rts, LO, (long)HI*LO, nullptr, 0);

    // out_b = X_b R_b + z_b  [2048,4096] K=512
    mma_gemm_h2<<<dim3(HI/128, Nn/128, Bb), 256, H2_SMEM>>>(
        LO, XhH, XhL, (long)Nn*LO, Rts, (long)HI*LO,
        out, nullptr, nullptr, nullptr, HI, (long)Nn*HI, z, HI);

    (void)in_sizes; (void)n_in; (void)out_size;
}

// round 16
// speedup vs baseline: 5.3533x; 1.3640x over previous
#include <cuda_runtime.h>
#include <cuda_bf16.h>
#include <cuda_fp16.h>
#include <cstdint>

// Shapes (fixed by the problem): B=8, N=2048, low=512, high=4096
#define Bb 8
#define Nn 2048
#define LO 512
#define HI 4096
#define BIGF 9.0e15f

// ---------------- fp32 scratch --------------------------------------------
__device__ float g_E[Bb*LO*HI];        // raw scores e' (pre-bias/scale)
__device__ float g_s[Bb*LO];
__device__ float g_u[Bb*LO];
__device__ float g_v[Bb*HI];
__device__ float g_w[Bb*HI];
__device__ float g_z[Bb*HI];

// ---------------- bf16 hi/lo operands (score chain, K-major) ----------------
__device__ __align__(256) __nv_bfloat16 g_XtH[Bb*LO*Nn];   // X^T per batch
__device__ __align__(256) __nv_bfloat16 g_XtL[Bb*LO*Nn];
__device__ __align__(256) __nv_bfloat16 g_WqH[LO*LO];
__device__ __align__(256) __nv_bfloat16 g_WqL[LO*LO];
__device__ __align__(256) __nv_bfloat16 g_WkH[HI*LO];
__device__ __align__(256) __nv_bfloat16 g_WkL[HI*LO];
__device__ __align__(256) __nv_bfloat16 g_GH [Bb*LO*LO];
__device__ __align__(256) __nv_bfloat16 g_GL [Bb*LO*LO];
__device__ __align__(256) __nv_bfloat16 g_TH [Bb*LO*LO];
__device__ __align__(256) __nv_bfloat16 g_TL [Bb*LO*LO];

// ---------------- fp16 operands (value chain, K-major) ----------------------
__device__ __align__(256) __half g_Os [HI*HI];     // O single
__device__ __align__(256) __half g_As [Bb*LO*HI];  // attn weights (single)
__device__ __align__(256) __half g_ShH[Bb*HI*LO];  // S = O A^T hi
__device__ __align__(256) __half g_ShL[Bb*HI*LO];  // S lo
__device__ __align__(256) __half g_WvTs[LO*LO];    // Wv^T (single)
__device__ __align__(256) __half g_Rts[Bb*HI*LO];  // R^T = S Wv (single)
__device__ __align__(256) __half g_Xs [Bb*Nn*LO];  // X single

// ---------------- PTX helpers ----------------------------------------------
__device__ __forceinline__ uint32_t s2u(const void* p) {
    uint32_t a;
    asm("{ .reg .u64 t; cvta.to.shared.u64 t, %1; cvt.u32.u64 %0, t; }" : "=r"(a) : "l"(p));
    return a;
}
// SW64 swizzle for 64-byte rows (conflict-free for ldmatrix + cp.async)
#define SWZ64(x) ((x) ^ (((x) >> 3) & 0x30))

__device__ __forceinline__ void cp16(uint32_t sa, const void* ga) {
    asm volatile("cp.async.cg.shared.global [%0], [%1], 16;" :: "r"(sa), "l"(ga));
}

__device__ __forceinline__ void ldsm4(uint32_t& r0, uint32_t& r1, uint32_t& r2,
                                      uint32_t& r3, uint32_t a) {
    asm volatile("ldmatrix.sync.aligned.m8n8.x4.shared.b16 {%0,%1,%2,%3}, [%4];"
        : "=r"(r0), "=r"(r1), "=r"(r2), "=r"(r3) : "r"(a));
}

__device__ __forceinline__ void mma16816(float* d, const uint32_t* a,
                                         uint32_t b0, uint32_t b1) {
    asm volatile(
        "mma.sync.aligned.m16n8k16.row.col.f32.bf16.bf16.f32 "
        "{%0,%1,%2,%3}, {%4,%5,%6,%7}, {%8,%9}, {%0,%1,%2,%3};"
        : "+f"(d[0]), "+f"(d[1]), "+f"(d[2]), "+f"(d[3])
        : "r"(a[0]), "r"(a[1]), "r"(a[2]), "r"(a[3]), "r"(b0), "r"(b1));
}

__device__ __forceinline__ void mma16816h(float* d, const uint32_t* a,
                                          uint32_t b0, uint32_t b1) {
    asm volatile(
        "mma.sync.aligned.m16n8k16.row.col.f32.f16.f16.f32 "
        "{%0,%1,%2,%3}, {%4,%5,%6,%7}, {%8,%9}, {%0,%1,%2,%3};"
        : "+f"(d[0]), "+f"(d[1]), "+f"(d[2]), "+f"(d[3])
        : "r"(a[0]), "r"(a[1]), "r"(a[2]), "r"(a[3]), "r"(b0), "r"(b1));
}

__device__ __forceinline__ __nv_bfloat162 split_pair(float x, float y, __nv_bfloat162& lo) {
    __nv_bfloat16 hx = __float2bfloat16(x);
    __nv_bfloat16 hy = __float2bfloat16(y);
    __nv_bfloat16 lx = __float2bfloat16(x - __bfloat162float(hx));
    __nv_bfloat16 ly = __float2bfloat16(y - __bfloat162float(hy));
    lo = __nv_bfloat162(lx, ly);
    return __nv_bfloat162(hx, hy);
}

__device__ __forceinline__ __half2 split_pair_h(float x, float y, __half2& lo) {
    __half hx = __float2half_rn(x), hy = __float2half_rn(y);
    __half lx = __float2half_rn(x - __half2float(hx));
    __half ly = __float2half_rn(y - __half2float(hy));
    lo = __halves2half2(lx, ly);
    return __halves2half2(hx, hy);
}

// ============================================================================
// bf16 engine (score chain): C = Ah·Bh^T + Al·Bh^T + Ah·Bl^T
// CTA 128x128, 256 thr, K-chunk 32 (64B rows, SW64), 3-stage, 2 CTAs/SM.
// ============================================================================
#define KCH 32
#define STAGE_T 8192
#define STAGE_BYTES 32768
#define GEMM_SMEM (3 * STAGE_BYTES)    // 98304

__global__ void __launch_bounds__(256, 2) mma_gemm(
    int K,
    const __nv_bfloat16* __restrict__ Ahi, const __nv_bfloat16* __restrict__ Alo, long sA,
    const __nv_bfloat16* __restrict__ Bhi, const __nv_bfloat16* __restrict__ Blo, long sB,
    float* __restrict__ C,
    __nv_bfloat16* __restrict__ Chi, __nv_bfloat16* __restrict__ Clo,
    int ldc, long sC)
{
    extern __shared__ char smem[];
    const uint32_t sb = s2u(smem);
    const int tid = threadIdx.x;
    const int wid = tid >> 5, lane = tid & 31;
    const int bz = blockIdx.z;
    const int row0 = blockIdx.y * 128;
    const int col0 = blockIdx.x * 128;
    Ahi += (long)bz * sA; Alo += (long)bz * sA;
    Bhi += (long)bz * sB; Blo += (long)bz * sB;

    const int warp_m = (wid & 3) * 32;
    const int warp_n = (wid >> 2) * 64;

    float acc[2][8][4];
#pragma unroll
    for (int mi = 0; mi < 2; mi++)
#pragma unroll
        for (int ni = 0; ni < 8; ni++)
#pragma unroll
            for (int q = 0; q < 4; q++) acc[mi][ni][q] = 0.f;

    const int NC = K / KCH;

    auto load_chunk = [&](int c, int s) {
        uint32_t st = sb + s * STAGE_BYTES;
        long k0 = (long)c * KCH;
#pragma unroll
        for (int i = 0; i < 8; i++) {
            int idx = tid + i * 256;
            int t = i >> 1;
            int j = idx & 511;
            int r = j >> 2, cj = j & 3;
            const __nv_bfloat16* src = (t == 0) ? Ahi : (t == 1) ? Alo
                                     : (t == 2) ? Bhi : Blo;
            int rb = (t < 2) ? row0 : col0;
            cp16(st + t * STAGE_T + SWZ64(r * 64 + cj * 16),
                 src + (long)(rb + r) * K + k0 + cj * 8);
        }
    };

    const int lrow = lane & 15;
    const int lcol = (lane >> 4) * 16;

    load_chunk(0, 0);
    asm volatile("cp.async.commit_group;" ::: "memory");
    load_chunk(1, 1);
    asm volatile("cp.async.commit_group;" ::: "memory");

    for (int c = 0; c < NC; c++) {
        asm volatile("cp.async.wait_group 1;" ::: "memory");
        __syncthreads();
        if (c + 2 < NC) load_chunk(c + 2, (c + 2) % 3);
        asm volatile("cp.async.commit_group;" ::: "memory");

        uint32_t st = sb + (c % 3) * STAGE_BYTES;
        uint32_t ahb = st, alb = st + STAGE_T;
        uint32_t bhb = st + 2 * STAGE_T, blb = st + 3 * STAGE_T;
#pragma unroll
        for (int ks = 0; ks < 2; ks++) {
            uint32_t afh[2][4], afl[2][4];
#pragma unroll
            for (int mi = 0; mi < 2; mi++) {
                uint32_t off = SWZ64((warp_m + mi * 16 + lrow) * 64 + ks * 32 + lcol);
                ldsm4(afh[mi][0], afh[mi][1], afh[mi][2], afh[mi][3], ahb + off);
                ldsm4(afl[mi][0], afl[mi][1], afl[mi][2], afl[mi][3], alb + off);
            }
#pragma unroll
            for (int nb = 0; nb < 4; nb++) {
                uint32_t off = SWZ64((warp_n + nb * 16 + lrow) * 64 + ks * 32 + lcol);
                uint32_t h0, h1, h2, h3, l0, l1, l2, l3;
                ldsm4(h0, h1, h2, h3, bhb + off);
                ldsm4(l0, l1, l2, l3, blb + off);
#pragma unroll
                for (int mi = 0; mi < 2; mi++) {
                    mma16816(acc[mi][2 * nb],     afh[mi], h0, h2);
                    mma16816(acc[mi][2 * nb + 1], afh[mi], h1, h3);
                    mma16816(acc[mi][2 * nb],     afl[mi], h0, h2);
                    mma16816(acc[mi][2 * nb + 1], afl[mi], h1, h3);
                    mma16816(acc[mi][2 * nb],     afh[mi], l0, l2);
                    mma16816(acc[mi][2 * nb + 1], afh[mi], l1, l3);
                }
            }
        }
    }

    const int cbase = col0 + warp_n + (lane & 3) * 2;
#pragma unroll
    for (int mi = 0; mi < 2; mi++) {
#pragma unroll
        for (int h = 0; h < 2; h++) {
            int row = row0 + warp_m + mi * 16 + (lane >> 2) + h * 8;
            long base = (long)bz * sC + (long)row * ldc + cbase;
            if (C) {
                float* cr = C + base;
#pragma unroll
                for (int ni = 0; ni < 8; ni++) {
                    float2 v;
                    v.x = acc[mi][ni][h * 2];
                    v.y = acc[mi][ni][h * 2 + 1];
                    *(float2*)(cr + ni * 8) = v;
                }
            }
            if (Chi) {
#pragma unroll
                for (int ni = 0; ni < 8; ni++) {
                    __nv_bfloat162 lo;
                    __nv_bfloat162 hi = split_pair(acc[mi][ni][h * 2],
                                                   acc[mi][ni][h * 2 + 1], lo);
                    *(__nv_bfloat162*)(Chi + base + ni * 8) = hi;
                    *(__nv_bfloat162*)(Clo + base + ni * 8) = lo;
                }
            }
        }
    }
}

// ============================================================================
// fp16 engine (value chain), templated on product count:
//   NPROD=1: C = As[M,K]·Bs[N,K]^T            (2 tiles/stage, 48 KB total)
//   NPROD=2: C = (Ah+Al)[M,K]·Bs[N,K]^T       (3 tiles/stage, 72 KB total)
// CTA 128x128, 256 thr, K-chunk 32, 3-stage, 2 CTAs/SM.
// ============================================================================
template <int NPROD>
__global__ void __launch_bounds__(256, 2) mma_gemm_h(
    int K,
    const __half* __restrict__ Ahi, const __half* __restrict__ Alo, long sA,
    const __half* __restrict__ Bs, long sB,
    float* __restrict__ C,
    __half* __restrict__ Chi, __half* __restrict__ Clo,
    __half* __restrict__ Cs,
    int ldc, long sC,
    const float* __restrict__ bias, long sBias)
{
    constexpr int NT = NPROD + 1;               // tiles per stage
    constexpr int H_STAGE = NT * STAGE_T;       // stage bytes

    extern __shared__ char smem[];
    const uint32_t sb = s2u(smem);
    const int tid = threadIdx.x;
    const int wid = tid >> 5, lane = tid & 31;
    const int bz = blockIdx.z;
    const int row0 = blockIdx.y * 128;
    const int col0 = blockIdx.x * 128;
    Ahi += (long)bz * sA;
    if (NPROD == 2) Alo += (long)bz * sA;
    Bs += (long)bz * sB;

    const int warp_m = (wid & 3) * 32;
    const int warp_n = (wid >> 2) * 64;

    float acc[2][8][4];
#pragma unroll
    for (int mi = 0; mi < 2; mi++)
#pragma unroll
        for (int ni = 0; ni < 8; ni++)
#pragma unroll
            for (int q = 0; q < 4; q++) acc[mi][ni][q] = 0.f;

    const int NC = K / KCH;

    auto load_chunk = [&](int c, int s) {
        uint32_t st = sb + s * H_STAGE;
        long k0 = (long)c * KCH;
#pragma unroll
        for (int i = 0; i < 2 * NT; i++) {
            int idx = tid + i * 256;
            int t = i >> 1;                      // tile index (compile-time)
            int j = idx & 511;
            int r = j >> 2, cj = j & 3;
            const __half* src = (t < NPROD) ? ((t == 0) ? Ahi : Alo) : Bs;
            int rb = (t < NPROD) ? row0 : col0;
            cp16(st + t * STAGE_T + SWZ64(r * 64 + cj * 16),
                 src + (long)(rb + r) * K + k0 + cj * 8);
        }
    };

    const int lrow = lane & 15;
    const int lcol = (lane >> 4) * 16;

    load_chunk(0, 0);
    asm volatile("cp.async.commit_group;" ::: "memory");
    load_chunk(1, 1);
    asm volatile("cp.async.commit_group;" ::: "memory");

    for (int c = 0; c < NC; c++) {
        asm volatile("cp.async.wait_group 1;" ::: "memory");
        __syncthreads();
        if (c + 2 < NC) load_chunk(c + 2, (c + 2) % 3);
        asm volatile("cp.async.commit_group;" ::: "memory");

        uint32_t st = sb + (c % 3) * H_STAGE;
        uint32_t ahb = st, alb = st + STAGE_T;
        uint32_t bb = st + NPROD * STAGE_T;
#pragma unroll
        for (int ks = 0; ks < 2; ks++) {
            uint32_t afh[2][4], afl[2][4];
#pragma unroll
            for (int mi = 0; mi < 2; mi++) {
                uint32_t off = SWZ64((warp_m + mi * 16 + lrow) * 64 + ks * 32 + lcol);
                ldsm4(afh[mi][0], afh[mi][1], afh[mi][2], afh[mi][3], ahb + off);
                if (NPROD == 2)
                    ldsm4(afl[mi][0], afl[mi][1], afl[mi][2], afl[mi][3], alb + off);
            }
#pragma unroll
            for (int nb = 0; nb < 4; nb++) {
                uint32_t off = SWZ64((warp_n + nb * 16 + lrow) * 64 + ks * 32 + lcol);
                uint32_t b0, b1, b2, b3;
                ldsm4(b0, b1, b2, b3, bb + off);
#pragma unroll
                for (int mi = 0; mi < 2; mi++) {
                    mma16816h(acc[mi][2 * nb],     afh[mi], b0, b2);
                    mma16816h(acc[mi][2 * nb + 1], afh[mi], b1, b3);
                    if (NPROD == 2) {
                        mma16816h(acc[mi][2 * nb],     afl[mi], b0, b2);
                        mma16816h(acc[mi][2 * nb + 1], afl[mi], b1, b3);
                    }
                }
            }
        }
    }

    const int cbase = col0 + warp_n + (lane & 3) * 2;
#pragma unroll
    for (int mi = 0; mi < 2; mi++) {
#pragma unroll
        for (int h = 0; h < 2; h++) {
            int row = row0 + warp_m + mi * 16 + (lane >> 2) + h * 8;
            long base = (long)bz * sC + (long)row * ldc + cbase;
            if (C) {
                float* cr = C + base;
                if (bias) {
                    const float* bp = bias + bz * sBias + cbase;
#pragma unroll
                    for (int ni = 0; ni < 8; ni++) {
                        float2 v;
                        v.x = acc[mi][ni][h * 2]     + bp[ni * 8];
                        v.y = acc[mi][ni][h * 2 + 1] + bp[ni * 8 + 1];
                        *(float2*)(cr + ni * 8) = v;
                    }
                } else {
#pragma unroll
                    for (int ni = 0; ni < 8; ni++) {
                        float2 v;
                        v.x = acc[mi][ni][h * 2];
                        v.y = acc[mi][ni][h * 2 + 1];
                        *(float2*)(cr + ni * 8) = v;
                    }
                }
            }
            if (Chi) {
#pragma unroll
                for (int ni = 0; ni < 8; ni++) {
                    __half2 lo;
                    __half2 hi = split_pair_h(acc[mi][ni][h * 2],
                                              acc[mi][ni][h * 2 + 1], lo);
                    *(__half2*)(Chi + base + ni * 8) = hi;
                    *(__half2*)(Clo + base + ni * 8) = lo;
                }
            }
            if (Cs) {
#pragma unroll
                for (int ni = 0; ni < 8; ni++) {
                    __half2 v = __halves2half2(__float2half_rn(acc[mi][ni][h * 2]),
                                               __float2half_rn(acc[mi][ni][h * 2 + 1]));
                    *(__half2*)(Cs + base + ni * 8) = v;
                }
            }
        }
    }
}

#define H1_SMEM (3 * 2 * STAGE_T)   // 49152
#define H2_SMEM (3 * 3 * STAGE_T)   // 73728

// ---------------- fp32 -> bf16 hi/lo split (coalesced) ----------------------
__global__ void split2_kernel(const float* __restrict__ src, long sS,
                              __nv_bfloat16* __restrict__ hi,
                              __nv_bfloat16* __restrict__ lo,
                              long sD, int pairs)
{
    int b = blockIdx.y;
    const float2* s2 = (const float2*)(src + (long)b * sS);
    __nv_bfloat162* h2 = (__nv_bfloat162*)(hi + (long)b * sD);
    __nv_bfloat162* l2 = (__nv_bfloat162*)(lo + (long)b * sD);
    for (int i = blockIdx.x * 256 + threadIdx.x; i < pairs; i += gridDim.x * 256) {
        float2 x = s2[i];
        __nv_bfloat162 lv;
        __nv_bfloat162 hv = split_pair(x.x, x.y, lv);
        h2[i] = hv;
        l2[i] = lv;
    }
}

// ---------------- fp32 -> fp16 single cast (coalesced) ----------------------
__global__ void castH_kernel(const float* __restrict__ src, long sS,
                             __half* __restrict__ dst, long sD, int pairs)
{
    int b = blockIdx.y;
    const float2* s2 = (const float2*)(src + (long)b * sS);
    __half2* d2 = (__half2*)(dst + (long)b * sD);
    for (int i = blockIdx.x * 256 + threadIdx.x; i < pairs; i += gridDim.x * 256) {
        float2 x = s2[i];
        d2[i] = __halves2half2(__float2half_rn(x.x), __float2half_rn(x.y));
    }
}

// transpose + split: src [R,C] -> hi/lo bf16 [C,R]
__global__ void tsplit2_kernel(const float* __restrict__ src, long sS,
                               __nv_bfloat16* __restrict__ hi,
                               __nv_bfloat16* __restrict__ lo,
                               long sD, int R, int C)
{
    __shared__ float t[32][33];
    int b = blockIdx.z;
    src += (long)b * sS;
    int r0 = blockIdx.y * 32, c0 = blockIdx.x * 32;
    int tx = threadIdx.x, ty = threadIdx.y;   // (32, 8)
#pragma unroll
    for (int i = 0; i < 4; i++)
        t[ty + 8 * i][tx] = src[(long)(r0 + ty + 8 * i) * C + c0 + tx];
    __syncthreads();
#pragma unroll
    for (int i = 0; i < 4; i++) {
        int cc = c0 + ty + 8 * i;
        int rr = r0 + tx;
        float x = t[tx][ty + 8 * i];
        __nv_bfloat16 h = __float2bfloat16(x);
        __nv_bfloat16 l = __float2bfloat16(x - __bfloat162float(h));
        long o = (long)b * sD + (long)cc * R + rr;
        hi[o] = h;
        lo[o] = l;
    }
}

// transpose: src [R,C] -> fp16 single [C,R]  (used for Wv^T only)
__global__ void tsplitH_kernel(const float* __restrict__ src,
                               __half* __restrict__ dst, int R, int C)
{
    __shared__ float t[32][33];
    int r0 = blockIdx.y * 32, c0 = blockIdx.x * 32;
    int tx = threadIdx.x, ty = threadIdx.y;   // (32, 8)
#pragma unroll
    for (int i = 0; i < 4; i++)
        t[ty + 8 * i][tx] = src[(long)(r0 + ty + 8 * i) * C + c0 + tx];
    __syncthreads();
#pragma unroll
    for (int i = 0; i < 4; i++) {
        int cc = c0 + ty + 8 * i;
        int rr = r0 + tx;
        dst[(long)cc * R + rr] = __float2half_rn(t[tx][ty + 8 * i]);
    }
}

// ---------------- small helper kernels --------------------------------------
__device__ __forceinline__ float warpSum(float v) {
#pragma unroll
    for (int o = 16; o; o >>= 1) v += __shfl_xor_sync(0xffffffffu, v, o);
    return v;
}

__global__ void colsum_kernel(const float* __restrict__ X, float* __restrict__ s) {
    int b = blockIdx.x, m = threadIdx.x;
    const float* xb = X + (long)b * Nn * LO;
    float acc = 0.f;
    for (int n = 0; n < Nn; n++) acc += xb[(long)n * LO + m];
    s[b * LO + m] = acc;
}

__global__ void rowdot_kernel(const float* __restrict__ W, const float* __restrict__ x,
                              float* __restrict__ out, int rows, int cols,
                              const float* __restrict__ addv) {
    int warp = threadIdx.x >> 5, lane = threadIdx.x & 31;
    int r = blockIdx.x * 8 + warp;
    int b = blockIdx.y;
    if (r >= rows) return;
    const float* xb = x + (long)b * cols;
    const float* wr = W + (long)r * cols;
    float s = 0.f;
    for (int c = lane; c < cols; c += 32) s += wr[c] * xb[c];
    s = warpSum(s);
    if (lane == 0) out[(long)b * rows + r] = s + (addv ? addv[r] : 0.f);
}

// w[b][h] = sum_l bv[l] * As[b,l,h]
__global__ void wvec_kernel(const __half* __restrict__ As,
                            const float* __restrict__ bv,
                            float* __restrict__ w) {
    int h = blockIdx.x * 256 + threadIdx.x;
    int b = blockIdx.y;
    const __half* Ab = As + (long)b * LO * HI;
    float acc = 0.f;
    for (int l = 0; l < LO; l++)
        acc += bv[l] * __half2float(Ab[(long)l * HI + h]);
    w[(long)b * HI + h] = acc;
}

// ---------------- fused softmax + min-max-norm attention combine ------------
// reads raw scores E, writes attn weights as single fp16
__global__ void __launch_bounds__(256) attn_kernel(
    const float* __restrict__ E, const int* __restrict__ linkage,
    const float* __restrict__ u, const float* __restrict__ bq,
    const float* __restrict__ v, const float* __restrict__ bk,
    __half* __restrict__ As)
{
    __shared__ float red[8];
    const int l = blockIdx.x, b = blockIdx.y;
    const float* row = E + ((long)(b * LO + l)) * HI;
    const int* lrow = linkage + (long)l * HI;
    const float* vb = v + (long)b * HI;
    const float uval = u[b * LO + l];
    const float bqv  = bq[l];

    float ev[16];
    unsigned mbits = 0;
    float gmax = -3.4e38f, mn = BIGF, mx = -BIGF;

#pragma unroll
    for (int j = 0; j < 16; j++) {
        int hh = threadIdx.x + j * 256;
        float bkh = bk[hh];
        float e = (row[hh] + uval * bkh + bqv * (vb[hh] + (float)Nn * bkh)) * 0.015625f;
        ev[j] = e;
        gmax = fmaxf(gmax, e);
        if (lrow[hh] > 0) {
            mbits |= 1u << j;
            mn = fminf(mn, e);
            mx = fmaxf(mx, e);
        }
    }

    const int wid = threadIdx.x >> 5, lane = threadIdx.x & 31;
#pragma unroll
    for (int o = 16; o; o >>= 1) gmax = fmaxf(gmax, __shfl_xor_sync(0xffffffffu, gmax, o));
    if (lane == 0) red[wid] = gmax;
    __syncthreads();
    gmax = red[0];
#pragma unroll
    for (int i = 1; i < 8; i++) gmax = fmaxf(gmax, red[i]);
    __syncthreads();

#pragma unroll
    for (int o = 16; o; o >>= 1) mn = fminf(mn, __shfl_xor_sync(0xffffffffu, mn, o));
    if (lane == 0) red[wid] = mn;
    __syncthreads();
    mn = red[0];
#pragma unroll
    for (int i = 1; i < 8; i++) mn = fminf(mn, red[i]);
    __syncthreads();

#pragma unroll
    for (int o = 16; o; o >>= 1) mx = fmaxf(mx, __shfl_xor_sync(0xffffffffu, mx, o));
    if (lane == 0) red[wid] = mx;
    __syncthreads();
    mx = red[0];
#pragma unroll
    for (int i = 1; i < 8; i++) mx = fmaxf(mx, red[i]);
    __syncthreads();

    float den = mx - mn;
    if (den == 0.0f) den = 1e-6f;
    const bool hasMask = (mx != -BIGF);
    const float lmax = hasMask ? (((mx - mn) == 0.0f) ? 0.0f : 1.0f) : -BIGF;

    float eg[16], el[16];
    float gsum = 0.f, lsum = 0.f;
#pragma unroll
    for (int j = 0; j < 16; j++) {
        float e = ev[j];
        float g = __expf(e - gmax);
        eg[j] = g;
        gsum += g;
        float lv = ((mbits >> j) & 1) ? (e - mn) / den : -BIGF;
        float ll = __expf(lv - lmax);
        el[j] = ll;
        lsum += ll;
    }

    gsum = warpSum(gsum);
    if (lane == 0) red[wid] = gsum;
    __syncthreads();
    gsum = red[0];
#pragma unroll
    for (int i = 1; i < 8; i++) gsum += red[i];
    __syncthreads();

    lsum = warpSum(lsum);
    if (lane == 0) red[wid] = lsum;
    __syncthreads();
    lsum = red[0];
#pragma unroll
    for (int i = 1; i < 8; i++) lsum += red[i];

    const float rg = 1.0f / gsum, rl = 1.0f / lsum;
    long obase = ((long)(b * LO + l)) * HI;
#pragma unroll
    for (int j = 0; j < 16; j++) {
        int hh = threadIdx.x + j * 256;
        As[obase + hh] = __float2half_rn(eg[j] * rg + el[j] * rl);
    }
}

// ---------------- host launch ------------------------------------------------
template <typename T>
static T* symaddr(const void* sym) {
    void* p = nullptr;
    cudaGetSymbolAddress(&p, sym);
    return (T*)p;
}

extern "C" void kernel_launch(void* const* d_in, const int* in_sizes, int n_in,
                              void* d_out, int out_size) {
    const float* X   = (const float*)d_in[0];
    const int*   lk  = (const int*)d_in[1];
    const float* wq  = (const float*)d_in[2];
    const float* bq  = (const float*)d_in[3];
    const float* wk  = (const float*)d_in[4];
    const float* bk  = (const float*)d_in[5];
    const float* wv  = (const float*)d_in[6];
    const float* bv  = (const float*)d_in[7];
    const float* ow  = (const float*)d_in[8];
    const float* ob  = (const float*)d_in[9];
    float* out = (float*)d_out;

    float* E = symaddr<float>(g_E);
    float* s = symaddr<float>(g_s);
    float* u = symaddr<float>(g_u);
    float* v = symaddr<float>(g_v);
    float* w = symaddr<float>(g_w);
    float* z = symaddr<float>(g_z);

    __nv_bfloat16* XtH = symaddr<__nv_bfloat16>(g_XtH);
    __nv_bfloat16* XtL = symaddr<__nv_bfloat16>(g_XtL);
    __nv_bfloat16* WqH = symaddr<__nv_bfloat16>(g_WqH);
    __nv_bfloat16* WqL = symaddr<__nv_bfloat16>(g_WqL);
    __nv_bfloat16* WkH = symaddr<__nv_bfloat16>(g_WkH);
    __nv_bfloat16* WkL = symaddr<__nv_bfloat16>(g_WkL);
    __nv_bfloat16* GH  = symaddr<__nv_bfloat16>(g_GH);
    __nv_bfloat16* GL  = symaddr<__nv_bfloat16>(g_GL);
    __nv_bfloat16* TH  = symaddr<__nv_bfloat16>(g_TH);
    __nv_bfloat16* TL  = symaddr<__nv_bfloat16>(g_TL);

    __half* Os   = symaddr<__half>(g_Os);
    __half* As   = symaddr<__half>(g_As);
    __half* ShH  = symaddr<__half>(g_ShH);
    __half* ShL  = symaddr<__half>(g_ShL);
    __half* WvTs = symaddr<__half>(g_WvTs);
    __half* Rts  = symaddr<__half>(g_Rts);
    __half* Xs   = symaddr<__half>(g_Xs);

    cudaFuncSetAttribute(mma_gemm, cudaFuncAttributeMaxDynamicSharedMemorySize, GEMM_SMEM);
    cudaFuncSetAttribute(mma_gemm_h<1>, cudaFuncAttributeMaxDynamicSharedMemorySize, H1_SMEM);
    cudaFuncSetAttribute(mma_gemm_h<2>, cudaFuncAttributeMaxDynamicSharedMemorySize, H2_SMEM);

    dim3 tb(32, 8);

    // input/weight conversions (one-time)
    tsplit2_kernel<<<dim3(LO/32, Nn/32, Bb), tb>>>(X, (long)Nn*LO, XtH, XtL, (long)LO*Nn, Nn, LO);
    castH_kernel<<<dim3(2048, Bb), 256>>>(X, (long)Nn*LO, Xs, (long)Nn*LO, Nn*LO/2);
    split2_kernel<<<dim3(512, 1), 256>>>(wq, 0, WqH, WqL, 0, LO*LO/2);
    split2_kernel<<<dim3(4096, 1), 256>>>(wk, 0, WkH, WkL, 0, HI*LO/2);
    tsplitH_kernel<<<dim3(LO/32, LO/32, 1), tb>>>(wv, WvTs, LO, LO);
    castH_kernel<<<dim3(8192, 1), 256>>>(ow, 0, Os, 0, HI*HI/2);

    // bias correction vectors (exact; zero-valued in this dataset)
    colsum_kernel<<<Bb, LO>>>(X, s);
    rowdot_kernel<<<dim3(LO/8, Bb), 256>>>(wq, s, u, LO, LO, nullptr);
    rowdot_kernel<<<dim3(HI/8, Bb), 256>>>(wk, s, v, HI, LO, nullptr);

    // -------- score chain (bf16x3) --------
    // G_b = Xt Xt^T   [512,512] K=2048  -> bf16 hi/lo split epilogue
    mma_gemm<<<dim3(LO/128, LO/128, Bb), 256, GEMM_SMEM>>>(
        Nn, XtH, XtL, (long)LO*Nn, XtH, XtL, (long)LO*Nn,
        nullptr, GH, GL, LO, (long)LO*LO);

    // T_b = Wq G_b
    mma_gemm<<<dim3(LO/128, LO/128, Bb), 256, GEMM_SMEM>>>(
        LO, WqH, WqL, 0, GH, GL, (long)LO*LO,
        nullptr, TH, TL, LO, (long)LO*LO);

    // E_b = T_b Wk^T  [512,4096] K=512  -> fp32
    mma_gemm<<<dim3(HI/128, LO/128, Bb), 256, GEMM_SMEM>>>(
        LO, TH, TL, (long)LO*LO, WkH, WkL, 0,
        E, nullptr, nullptr, HI, (long)LO*HI);

    // A_b = softmax(e) + softmax(minmaxnorm(e, mask)) -> single fp16
    attn_kernel<<<dim3(LO, Bb), 256>>>(E, lk, u, bq, v, bk, As);

    // bias path: w_b = bv^T A_b ; z_b = w_b O^T + o_b
    wvec_kernel<<<dim3(HI/256, Bb), 256>>>(As, bv, w);
    rowdot_kernel<<<dim3(HI/8, Bb), 256>>>(ow, w, z, HI, HI, ob);

    // -------- value chain (fp16) --------
    // S_b = O A_b^T   [4096,512] K=4096 (dominant, single x single) -> hi/lo
    mma_gemm_h<1><<<dim3(LO/128, HI/128, Bb), 256, H1_SMEM>>>(
        HI, Os, nullptr, 0, As, (long)LO*HI,
        nullptr, ShH, ShL, nullptr, LO, (long)HI*LO, nullptr, 0);

    // Rt_b = S_b Wv   [4096,512] K=512 (2-product) -> single fp16 epilogue
    mma_gemm_h<2><<<dim3(LO/128, HI/128, Bb), 256, H2_SMEM>>>(
        LO, ShH, ShL, (long)HI*LO, WvTs, 0,
        nullptr, nullptr, nullptr, Rts, LO, (long)HI*LO, nullptr, 0);

    // out_b = X_b R_b + z_b  [2048,4096] K=512 (single x single)
    mma_gemm_h<1><<<dim3(HI/128, Nn/128, Bb), 256, H1_SMEM>>>(
        LO, Xs, nullptr, (long)Nn*LO, Rts, (long)HI*LO,
        out, nullptr, nullptr, nullptr, HI, (long)Nn*HI, z, HI);

    (void)in_sizes; (void)n_in; (void)out_size;
}

// round 17
// speedup vs baseline: 5.9925x; 1.1194x over previous
#include <cuda_runtime.h>
#include <cuda_bf16.h>
#include <cuda_fp16.h>
#include <cstdint>

// Shapes (fixed by the problem): B=8, N=2048, low=512, high=4096
#define Bb 8
#define Nn 2048
#define LO 512
#define HI 4096
#define BIGF 9.0e15f

// ---------------- fp32 scratch --------------------------------------------
__device__ float g_E[Bb*LO*HI];        // raw scores e' (pre-bias/scale)
__device__ float g_s[Bb*LO];
__device__ float g_u[Bb*LO];
__device__ float g_v[Bb*HI];
__device__ float g_w[Bb*HI];
__device__ float g_z[Bb*HI];

// ---------------- bf16 hi/lo operands (score chain, K-major) ----------------
__device__ __align__(256) __nv_bfloat16 g_XtH[Bb*LO*Nn];   // X^T per batch
__device__ __align__(256) __nv_bfloat16 g_XtL[Bb*LO*Nn];
__device__ __align__(256) __nv_bfloat16 g_WqH[LO*LO];
__device__ __align__(256) __nv_bfloat16 g_WqL[LO*LO];
__device__ __align__(256) __nv_bfloat16 g_WkH[HI*LO];
__device__ __align__(256) __nv_bfloat16 g_WkL[HI*LO];
__device__ __align__(256) __nv_bfloat16 g_GH [Bb*LO*LO];
__device__ __align__(256) __nv_bfloat16 g_GL [Bb*LO*LO];
__device__ __align__(256) __nv_bfloat16 g_TH [Bb*LO*LO];
__device__ __align__(256) __nv_bfloat16 g_TL [Bb*LO*LO];

// ---------------- fp16 operands (value chain, K-major) ----------------------
__device__ __align__(256) __half g_Os [HI*HI];     // O single
__device__ __align__(256) __half g_As [Bb*LO*HI];  // attn weights (single)
__device__ __align__(256) __half g_Ss [Bb*HI*LO];  // S = O A^T (single)
__device__ __align__(256) __half g_WvTs[LO*LO];    // Wv^T (single)
__device__ __align__(256) __half g_Rts[Bb*HI*LO];  // R^T = S Wv (single)
__device__ __align__(256) __half g_Xs [Bb*Nn*LO];  // X single

// ---------------- PTX helpers ----------------------------------------------
__device__ __forceinline__ uint32_t s2u(const void* p) {
    uint32_t a;
    asm("{ .reg .u64 t; cvta.to.shared.u64 t, %1; cvt.u32.u64 %0, t; }" : "=r"(a) : "l"(p));
    return a;
}
// SW64 swizzle for 64-byte rows (conflict-free for ldmatrix + cp.async)
#define SWZ64(x) ((x) ^ (((x) >> 3) & 0x30))

__device__ __forceinline__ void cp16(uint32_t sa, const void* ga) {
    asm volatile("cp.async.cg.shared.global [%0], [%1], 16;" :: "r"(sa), "l"(ga));
}

__device__ __forceinline__ void ldsm4(uint32_t& r0, uint32_t& r1, uint32_t& r2,
                                      uint32_t& r3, uint32_t a) {
    asm volatile("ldmatrix.sync.aligned.m8n8.x4.shared.b16 {%0,%1,%2,%3}, [%4];"
        : "=r"(r0), "=r"(r1), "=r"(r2), "=r"(r3) : "r"(a));
}

__device__ __forceinline__ void mma16816(float* d, const uint32_t* a,
                                         uint32_t b0, uint32_t b1) {
    asm volatile(
        "mma.sync.aligned.m16n8k16.row.col.f32.bf16.bf16.f32 "
        "{%0,%1,%2,%3}, {%4,%5,%6,%7}, {%8,%9}, {%0,%1,%2,%3};"
        : "+f"(d[0]), "+f"(d[1]), "+f"(d[2]), "+f"(d[3])
        : "r"(a[0]), "r"(a[1]), "r"(a[2]), "r"(a[3]), "r"(b0), "r"(b1));
}

__device__ __forceinline__ void mma16816h(float* d, const uint32_t* a,
                                          uint32_t b0, uint32_t b1) {
    asm volatile(
        "mma.sync.aligned.m16n8k16.row.col.f32.f16.f16.f32 "
        "{%0,%1,%2,%3}, {%4,%5,%6,%7}, {%8,%9}, {%0,%1,%2,%3};"
        : "+f"(d[0]), "+f"(d[1]), "+f"(d[2]), "+f"(d[3])
        : "r"(a[0]), "r"(a[1]), "r"(a[2]), "r"(a[3]), "r"(b0), "r"(b1));
}

__device__ __forceinline__ __nv_bfloat162 split_pair(float x, float y, __nv_bfloat162& lo) {
    __nv_bfloat16 hx = __float2bfloat16(x);
    __nv_bfloat16 hy = __float2bfloat16(y);
    __nv_bfloat16 lx = __float2bfloat16(x - __bfloat162float(hx));
    __nv_bfloat16 ly = __float2bfloat16(y - __bfloat162float(hy));
    lo = __nv_bfloat162(lx, ly);
    return __nv_bfloat162(hx, hy);
}

__device__ __forceinline__ __half2 split_pair_h(float x, float y, __half2& lo) {
    __half hx = __float2half_rn(x), hy = __float2half_rn(y);
    __half lx = __float2half_rn(x - __half2float(hx));
    __half ly = __float2half_rn(y - __half2float(hy));
    lo = __halves2half2(lx, ly);
    return __halves2half2(hx, hy);
}

// ============================================================================
// bf16 engine (score chain): C = Ah·Bh^T + Al·Bh^T + Ah·Bl^T
// CTA 128x128, 256 thr, K-chunk 32 (64B rows, SW64), 3-stage, 2 CTAs/SM.
// ============================================================================
#define KCH 32
#define STAGE_T 8192
#define STAGE_BYTES 32768
#define GEMM_SMEM (3 * STAGE_BYTES)    // 98304

__global__ void __launch_bounds__(256, 2) mma_gemm(
    int K,
    const __nv_bfloat16* __restrict__ Ahi, const __nv_bfloat16* __restrict__ Alo, long sA,
    const __nv_bfloat16* __restrict__ Bhi, const __nv_bfloat16* __restrict__ Blo, long sB,
    float* __restrict__ C,
    __nv_bfloat16* __restrict__ Chi, __nv_bfloat16* __restrict__ Clo,
    int ldc, long sC)
{
    extern __shared__ char smem[];
    const uint32_t sb = s2u(smem);
    const int tid = threadIdx.x;
    const int wid = tid >> 5, lane = tid & 31;
    const int bz = blockIdx.z;
    const int row0 = blockIdx.y * 128;
    const int col0 = blockIdx.x * 128;
    Ahi += (long)bz * sA; Alo += (long)bz * sA;
    Bhi += (long)bz * sB; Blo += (long)bz * sB;

    const int warp_m = (wid & 3) * 32;
    const int warp_n = (wid >> 2) * 64;

    float acc[2][8][4];
#pragma unroll
    for (int mi = 0; mi < 2; mi++)
#pragma unroll
        for (int ni = 0; ni < 8; ni++)
#pragma unroll
            for (int q = 0; q < 4; q++) acc[mi][ni][q] = 0.f;

    const int NC = K / KCH;

    auto load_chunk = [&](int c, int s) {
        uint32_t st = sb + s * STAGE_BYTES;
        long k0 = (long)c * KCH;
#pragma unroll
        for (int i = 0; i < 8; i++) {
            int idx = tid + i * 256;
            int t = i >> 1;
            int j = idx & 511;
            int r = j >> 2, cj = j & 3;
            const __nv_bfloat16* src = (t == 0) ? Ahi : (t == 1) ? Alo
                                     : (t == 2) ? Bhi : Blo;
            int rb = (t < 2) ? row0 : col0;
            cp16(st + t * STAGE_T + SWZ64(r * 64 + cj * 16),
                 src + (long)(rb + r) * K + k0 + cj * 8);
        }
    };

    const int lrow = lane & 15;
    const int lcol = (lane >> 4) * 16;

    load_chunk(0, 0);
    asm volatile("cp.async.commit_group;" ::: "memory");
    load_chunk(1, 1);
    asm volatile("cp.async.commit_group;" ::: "memory");

    for (int c = 0; c < NC; c++) {
        asm volatile("cp.async.wait_group 1;" ::: "memory");
        __syncthreads();
        if (c + 2 < NC) load_chunk(c + 2, (c + 2) % 3);
        asm volatile("cp.async.commit_group;" ::: "memory");

        uint32_t st = sb + (c % 3) * STAGE_BYTES;
        uint32_t ahb = st, alb = st + STAGE_T;
        uint32_t bhb = st + 2 * STAGE_T, blb = st + 3 * STAGE_T;
#pragma unroll
        for (int ks = 0; ks < 2; ks++) {
            uint32_t afh[2][4], afl[2][4];
#pragma unroll
            for (int mi = 0; mi < 2; mi++) {
                uint32_t off = SWZ64((warp_m + mi * 16 + lrow) * 64 + ks * 32 + lcol);
                ldsm4(afh[mi][0], afh[mi][1], afh[mi][2], afh[mi][3], ahb + off);
                ldsm4(afl[mi][0], afl[mi][1], afl[mi][2], afl[mi][3], alb + off);
            }
#pragma unroll
            for (int nb = 0; nb < 4; nb++) {
                uint32_t off = SWZ64((warp_n + nb * 16 + lrow) * 64 + ks * 32 + lcol);
                uint32_t h0, h1, h2, h3, l0, l1, l2, l3;
                ldsm4(h0, h1, h2, h3, bhb + off);
                ldsm4(l0, l1, l2, l3, blb + off);
#pragma unroll
                for (int mi = 0; mi < 2; mi++) {
                    mma16816(acc[mi][2 * nb],     afh[mi], h0, h2);
                    mma16816(acc[mi][2 * nb + 1], afh[mi], h1, h3);
                    mma16816(acc[mi][2 * nb],     afl[mi], h0, h2);
                    mma16816(acc[mi][2 * nb + 1], afl[mi], h1, h3);
                    mma16816(acc[mi][2 * nb],     afh[mi], l0, l2);
                    mma16816(acc[mi][2 * nb + 1], afh[mi], l1, l3);
                }
            }
        }
    }

    const int cbase = col0 + warp_n + (lane & 3) * 2;
#pragma unroll
    for (int mi = 0; mi < 2; mi++) {
#pragma unroll
        for (int h = 0; h < 2; h++) {
            int row = row0 + warp_m + mi * 16 + (lane >> 2) + h * 8;
            long base = (long)bz * sC + (long)row * ldc + cbase;
            if (C) {
                float* cr = C + base;
#pragma unroll
                for (int ni = 0; ni < 8; ni++) {
                    float2 v;
                    v.x = acc[mi][ni][h * 2];
                    v.y = acc[mi][ni][h * 2 + 1];
                    *(float2*)(cr + ni * 8) = v;
                }
            }
            if (Chi) {
#pragma unroll
                for (int ni = 0; ni < 8; ni++) {
                    __nv_bfloat162 lo;
                    __nv_bfloat162 hi = split_pair(acc[mi][ni][h * 2],
                                                   acc[mi][ni][h * 2 + 1], lo);
                    *(__nv_bfloat162*)(Chi + base + ni * 8) = hi;
                    *(__nv_bfloat162*)(Clo + base + ni * 8) = lo;
                }
            }
        }
    }
}

// ============================================================================
// fp16 engine (value chain), templated on product count:
//   NPROD=1: C = As[M,K]·Bs[N,K]^T            (2 tiles/stage, 48 KB total)
//   NPROD=2: C = (Ah+Al)[M,K]·Bs[N,K]^T       (3 tiles/stage, 72 KB total)
// CTA 128x128, 256 thr, K-chunk 32, 3-stage, 2 CTAs/SM.
// ============================================================================
template <int NPROD>
__global__ void __launch_bounds__(256, 2) mma_gemm_h(
    int K,
    const __half* __restrict__ Ahi, const __half* __restrict__ Alo, long sA,
    const __half* __restrict__ Bs, long sB,
    float* __restrict__ C,
    __half* __restrict__ Chi, __half* __restrict__ Clo,
    __half* __restrict__ Cs,
    int ldc, long sC,
    const float* __restrict__ bias, long sBias)
{
    constexpr int NT = NPROD + 1;               // tiles per stage
    constexpr int H_STAGE = NT * STAGE_T;       // stage bytes

    extern __shared__ char smem[];
    const uint32_t sb = s2u(smem);
    const int tid = threadIdx.x;
    const int wid = tid >> 5, lane = tid & 31;
    const int bz = blockIdx.z;
    const int row0 = blockIdx.y * 128;
    const int col0 = blockIdx.x * 128;
    Ahi += (long)bz * sA;
    if (NPROD == 2) Alo += (long)bz * sA;
    Bs += (long)bz * sB;

    const int warp_m = (wid & 3) * 32;
    const int warp_n = (wid >> 2) * 64;

    float acc[2][8][4];
#pragma unroll
    for (int mi = 0; mi < 2; mi++)
#pragma unroll
        for (int ni = 0; ni < 8; ni++)
#pragma unroll
            for (int q = 0; q < 4; q++) acc[mi][ni][q] = 0.f;

    const int NC = K / KCH;

    auto load_chunk = [&](int c, int s) {
        uint32_t st = sb + s * H_STAGE;
        long k0 = (long)c * KCH;
#pragma unroll
        for (int i = 0; i < 2 * NT; i++) {
            int idx = tid + i * 256;
            int t = i >> 1;                      // tile index (compile-time)
            int j = idx & 511;
            int r = j >> 2, cj = j & 3;
            const __half* src = (t < NPROD) ? ((t == 0) ? Ahi : Alo) : Bs;
            int rb = (t < NPROD) ? row0 : col0;
            cp16(st + t * STAGE_T + SWZ64(r * 64 + cj * 16),
                 src + (long)(rb + r) * K + k0 + cj * 8);
        }
    };

    const int lrow = lane & 15;
    const int lcol = (lane >> 4) * 16;

    load_chunk(0, 0);
    asm volatile("cp.async.commit_group;" ::: "memory");
    load_chunk(1, 1);
    asm volatile("cp.async.commit_group;" ::: "memory");

    for (int c = 0; c < NC; c++) {
        asm volatile("cp.async.wait_group 1;" ::: "memory");
        __syncthreads();
        if (c + 2 < NC) load_chunk(c + 2, (c + 2) % 3);
        asm volatile("cp.async.commit_group;" ::: "memory");

        uint32_t st = sb + (c % 3) * H_STAGE;
        uint32_t ahb = st, alb = st + STAGE_T;
        uint32_t bb = st + NPROD * STAGE_T;
#pragma unroll
        for (int ks = 0; ks < 2; ks++) {
            uint32_t afh[2][4], afl[2][4];
#pragma unroll
            for (int mi = 0; mi < 2; mi++) {
                uint32_t off = SWZ64((warp_m + mi * 16 + lrow) * 64 + ks * 32 + lcol);
                ldsm4(afh[mi][0], afh[mi][1], afh[mi][2], afh[mi][3], ahb + off);
                if (NPROD == 2)
                    ldsm4(afl[mi][0], afl[mi][1], afl[mi][2], afl[mi][3], alb + off);
            }
#pragma unroll
            for (int nb = 0; nb < 4; nb++) {
                uint32_t off = SWZ64((warp_n + nb * 16 + lrow) * 64 + ks * 32 + lcol);
                uint32_t b0, b1, b2, b3;
                ldsm4(b0, b1, b2, b3, bb + off);
#pragma unroll
                for (int mi = 0; mi < 2; mi++) {
                    mma16816h(acc[mi][2 * nb],     afh[mi], b0, b2);
                    mma16816h(acc[mi][2 * nb + 1], afh[mi], b1, b3);
                    if (NPROD == 2) {
                        mma16816h(acc[mi][2 * nb],     afl[mi], b0, b2);
                        mma16816h(acc[mi][2 * nb + 1], afl[mi], b1, b3);
                    }
                }
            }
        }
    }

    const int cbase = col0 + warp_n + (lane & 3) * 2;
#pragma unroll
    for (int mi = 0; mi < 2; mi++) {
#pragma unroll
        for (int h = 0; h < 2; h++) {
            int row = row0 + warp_m + mi * 16 + (lane >> 2) + h * 8;
            long base = (long)bz * sC + (long)row * ldc + cbase;
            if (C) {
                float* cr = C + base;
                if (bias) {
                    const float* bp = bias + bz * sBias + cbase;
#pragma unroll
                    for (int ni = 0; ni < 8; ni++) {
                        float2 v;
                        v.x = acc[mi][ni][h * 2]     + bp[ni * 8];
                        v.y = acc[mi][ni][h * 2 + 1] + bp[ni * 8 + 1];
                        *(float2*)(cr + ni * 8) = v;
                    }
                } else {
#pragma unroll
                    for (int ni = 0; ni < 8; ni++) {
                        float2 v;
                        v.x = acc[mi][ni][h * 2];
                        v.y = acc[mi][ni][h * 2 + 1];
                        *(float2*)(cr + ni * 8) = v;
                    }
                }
            }
            if (Cs) {
#pragma unroll
                for (int ni = 0; ni < 8; ni++) {
                    __half2 v = __halves2half2(__float2half_rn(acc[mi][ni][h * 2]),
                                               __float2half_rn(acc[mi][ni][h * 2 + 1]));
                    *(__half2*)(Cs + base + ni * 8) = v;
                }
            }
        }
    }
}

#define H1_SMEM (3 * 2 * STAGE_T)   // 49152
#define H2_SMEM (3 * 3 * STAGE_T)   // 73728

// ---------------- fp32 -> bf16 hi/lo split (coalesced) ----------------------
__global__ void split2_kernel(const float* __restrict__ src, long sS,
                              __nv_bfloat16* __restrict__ hi,
                              __nv_bfloat16* __restrict__ lo,
                              long sD, int pairs)
{
    int b = blockIdx.y;
    const float2* s2 = (const float2*)(src + (long)b * sS);
    __nv_bfloat162* h2 = (__nv_bfloat162*)(hi + (long)b * sD);
    __nv_bfloat162* l2 = (__nv_bfloat162*)(lo + (long)b * sD);
    for (int i = blockIdx.x * 256 + threadIdx.x; i < pairs; i += gridDim.x * 256) {
        float2 x = s2[i];
        __nv_bfloat162 lv;
        __nv_bfloat162 hv = split_pair(x.x, x.y, lv);
        h2[i] = hv;
        l2[i] = lv;
    }
}

// ---------------- fp32 -> fp16 single cast (coalesced) ----------------------
__global__ void castH_kernel(const float* __restrict__ src, long sS,
                             __half* __restrict__ dst, long sD, int pairs)
{
    int b = blockIdx.y;
    const float2* s2 = (const float2*)(src + (long)b * sS);
    __half2* d2 = (__half2*)(dst + (long)b * sD);
    for (int i = blockIdx.x * 256 + threadIdx.x; i < pairs; i += gridDim.x * 256) {
        float2 x = s2[i];
        d2[i] = __halves2half2(__float2half_rn(x.x), __float2half_rn(x.y));
    }
}

// transpose + split: src [R,C] -> hi/lo bf16 [C,R]
__global__ void tsplit2_kernel(const float* __restrict__ src, long sS,
                               __nv_bfloat16* __restrict__ hi,
                               __nv_bfloat16* __restrict__ lo,
                               long sD, int R, int C)
{
    __shared__ float t[32][33];
    int b = blockIdx.z;
    src += (long)b * sS;
    int r0 = blockIdx.y * 32, c0 = blockIdx.x * 32;
    int tx = threadIdx.x, ty = threadIdx.y;   // (32, 8)
#pragma unroll
    for (int i = 0; i < 4; i++)
        t[ty + 8 * i][tx] = src[(long)(r0 + ty + 8 * i) * C + c0 + tx];
    __syncthreads();
#pragma unroll
    for (int i = 0; i < 4; i++) {
        int cc = c0 + ty + 8 * i;
        int rr = r0 + tx;
        float x = t[tx][ty + 8 * i];
        __nv_bfloat16 h = __float2bfloat16(x);
        __nv_bfloat16 l = __float2bfloat16(x - __bfloat162float(h));
        long o = (long)b * sD + (long)cc * R + rr;
        hi[o] = h;
        lo[o] = l;
    }
}

// transpose: src [R,C] -> fp16 single [C,R]  (used for Wv^T only)
__global__ void tsplitH_kernel(const float* __restrict__ src,
                               __half* __restrict__ dst, int R, int C)
{
    __shared__ float t[32][33];
    int r0 = blockIdx.y * 32, c0 = blockIdx.x * 32;
    int tx = threadIdx.x, ty = threadIdx.y;   // (32, 8)
#pragma unroll
    for (int i = 0; i < 4; i++)
        t[ty + 8 * i][tx] = src[(long)(r0 + ty + 8 * i) * C + c0 + tx];
    __syncthreads();
#pragma unroll
    for (int i = 0; i < 4; i++) {
        int cc = c0 + ty + 8 * i;
        int rr = r0 + tx;
        dst[(long)cc * R + rr] = __float2half_rn(t[tx][ty + 8 * i]);
    }
}

// ---------------- small helper kernels --------------------------------------
__device__ __forceinline__ float warpSum(float v) {
#pragma unroll
    for (int o = 16; o; o >>= 1) v += __shfl_xor_sync(0xffffffffu, v, o);
    return v;
}

__global__ void zero_kernel(float* __restrict__ p, int n) {
    int i = blockIdx.x * 256 + threadIdx.x;
    if (i < n) p[i] = 0.f;
}

// parallel colsum: grid (32, Bb), each block sums 64 n-rows, atomicAdd into s
__global__ void colsum_kernel(const float* __restrict__ X, float* __restrict__ s) {
    int b = blockIdx.y, chunk = blockIdx.x, m = threadIdx.x;  // 512 threads
    const float* xb = X + (long)b * Nn * LO + (long)chunk * 64 * LO;
    float acc = 0.f;
#pragma unroll 4
    for (int n = 0; n < 64; n++) acc += xb[(long)n * LO + m];
    atomicAdd(&s[b * LO + m], acc);
}

__global__ void rowdot_kernel(const float* __restrict__ W, const float* __restrict__ x,
                              float* __restrict__ out, int rows, int cols,
                              const float* __restrict__ addv) {
    int warp = threadIdx.x >> 5, lane = threadIdx.x & 31;
    int r = blockIdx.x * 8 + warp;
    int b = blockIdx.y;
    if (r >= rows) return;
    const float* xb = x + (long)b * cols;
    const float* wr = W + (long)r * cols;
    float s = 0.f;
    for (int c = lane; c < cols; c += 32) s += wr[c] * xb[c];
    s = warpSum(s);
    if (lane == 0) out[(long)b * rows + r] = s + (addv ? addv[r] : 0.f);
}

// w[b][h] = sum_l bv[l] * As[b,l,h]
__global__ void wvec_kernel(const __half* __restrict__ As,
                            const float* __restrict__ bv,
                            float* __restrict__ w) {
    int h = blockIdx.x * 256 + threadIdx.x;
    int b = blockIdx.y;
    const __half* Ab = As + (long)b * LO * HI;
    float acc = 0.f;
    for (int l = 0; l < LO; l++)
        acc += bv[l] * __half2float(Ab[(long)l * HI + h]);
    w[(long)b * HI + h] = acc;
}

// ---------------- fused softmax + min-max-norm attention combine ------------
// reads raw scores E, writes attn weights as single fp16
__global__ void __launch_bounds__(256) attn_kernel(
    const float* __restrict__ E, const int* __restrict__ linkage,
    const float* __restrict__ u, const float* __restrict__ bq,
    const float* __restrict__ v, const float* __restrict__ bk,
    __half* __restrict__ As)
{
    __shared__ float red[8];
    const int l = blockIdx.x, b = blockIdx.y;
    const float* row = E + ((long)(b * LO + l)) * HI;
    const int* lrow = linkage + (long)l * HI;
    const float* vb = v + (long)b * HI;
    const float uval = u[b * LO + l];
    const float bqv  = bq[l];

    float ev[16];
    unsigned mbits = 0;
    float gmax = -3.4e38f, mn = BIGF, mx = -BIGF;

#pragma unroll
    for (int j = 0; j < 16; j++) {
        int hh = threadIdx.x + j * 256;
        float bkh = bk[hh];
        float e = (row[hh] + uval * bkh + bqv * (vb[hh] + (float)Nn * bkh)) * 0.015625f;
        ev[j] = e;
        gmax = fmaxf(gmax, e);
        if (lrow[hh] > 0) {
            mbits |= 1u << j;
            mn = fminf(mn, e);
            mx = fmaxf(mx, e);
        }
    }

    const int wid = threadIdx.x >> 5, lane = threadIdx.x & 31;
#pragma unroll
    for (int o = 16; o; o >>= 1) gmax = fmaxf(gmax, __shfl_xor_sync(0xffffffffu, gmax, o));
    if (lane == 0) red[wid] = gmax;
    __syncthreads();
    gmax = red[0];
#pragma unroll
    for (int i = 1; i < 8; i++) gmax = fmaxf(gmax, red[i]);
    __syncthreads();

#pragma unroll
    for (int o = 16; o; o >>= 1) mn = fminf(mn, __shfl_xor_sync(0xffffffffu, mn, o));
    if (lane == 0) red[wid] = mn;
    __syncthreads();
    mn = red[0];
#pragma unroll
    for (int i = 1; i < 8; i++) mn = fminf(mn, red[i]);
    __syncthreads();

#pragma unroll
    for (int o = 16; o; o >>= 1) mx = fmaxf(mx, __shfl_xor_sync(0xffffffffu, mx, o));
    if (lane == 0) red[wid] = mx;
    __syncthreads();
    mx = red[0];
#pragma unroll
    for (int i = 1; i < 8; i++) mx = fmaxf(mx, red[i]);
    __syncthreads();

    float den = mx - mn;
    if (den == 0.0f) den = 1e-6f;
    const bool hasMask = (mx != -BIGF);
    const float lmax = hasMask ? (((mx - mn) == 0.0f) ? 0.0f : 1.0f) : -BIGF;

    float eg[16], el[16];
    float gsum = 0.f, lsum = 0.f;
#pragma unroll
    for (int j = 0; j < 16; j++) {
        float e = ev[j];
        float g = __expf(e - gmax);
        eg[j] = g;
        gsum += g;
        float lv = ((mbits >> j) & 1) ? (e - mn) / den : -BIGF;
        float ll = __expf(lv - lmax);
        el[j] = ll;
        lsum += ll;
    }

    gsum = warpSum(gsum);
    if (lane == 0) red[wid] = gsum;
    __syncthreads();
    gsum = red[0];
#pragma unroll
    for (int i = 1; i < 8; i++) gsum += red[i];
    __syncthreads();

    lsum = warpSum(lsum);
    if (lane == 0) red[wid] = lsum;
    __syncthreads();
    lsum = red[0];
#pragma unroll
    for (int i = 1; i < 8; i++) lsum += red[i];

    const float rg = 1.0f / gsum, rl = 1.0f / lsum;
    long obase = ((long)(b * LO + l)) * HI;
#pragma unroll
    for (int j = 0; j < 16; j++) {
        int hh = threadIdx.x + j * 256;
        As[obase + hh] = __float2half_rn(eg[j] * rg + el[j] * rl);
    }
}

// ---------------- host launch ------------------------------------------------
template <typename T>
static T* symaddr(const void* sym) {
    void* p = nullptr;
    cudaGetSymbolAddress(&p, sym);
    return (T*)p;
}

extern "C" void kernel_launch(void* const* d_in, const int* in_sizes, int n_in,
                              void* d_out, int out_size) {
    const float* X   = (const float*)d_in[0];
    const int*   lk  = (const int*)d_in[1];
    const float* wq  = (const float*)d_in[2];
    const float* bq  = (const float*)d_in[3];
    const float* wk  = (const float*)d_in[4];
    const float* bk  = (const float*)d_in[5];
    const float* wv  = (const float*)d_in[6];
    const float* bv  = (const float*)d_in[7];
    const float* ow  = (const float*)d_in[8];
    const float* ob  = (const float*)d_in[9];
    float* out = (float*)d_out;

    float* E = symaddr<float>(g_E);
    float* s = symaddr<float>(g_s);
    float* u = symaddr<float>(g_u);
    float* v = symaddr<float>(g_v);
    float* w = symaddr<float>(g_w);
    float* z = symaddr<float>(g_z);

    __nv_bfloat16* XtH = symaddr<__nv_bfloat16>(g_XtH);
    __nv_bfloat16* XtL = symaddr<__nv_bfloat16>(g_XtL);
    __nv_bfloat16* WqH = symaddr<__nv_bfloat16>(g_WqH);
    __nv_bfloat16* WqL = symaddr<__nv_bfloat16>(g_WqL);
    __nv_bfloat16* WkH = symaddr<__nv_bfloat16>(g_WkH);
    __nv_bfloat16* WkL = symaddr<__nv_bfloat16>(g_WkL);
    __nv_bfloat16* GH  = symaddr<__nv_bfloat16>(g_GH);
    __nv_bfloat16* GL  = symaddr<__nv_bfloat16>(g_GL);
    __nv_bfloat16* TH  = symaddr<__nv_bfloat16>(g_TH);
    __nv_bfloat16* TL  = symaddr<__nv_bfloat16>(g_TL);

    __half* Os   = symaddr<__half>(g_Os);
    __half* As   = symaddr<__half>(g_As);
    __half* Ss   = symaddr<__half>(g_Ss);
    __half* WvTs = symaddr<__half>(g_WvTs);
    __half* Rts  = symaddr<__half>(g_Rts);
    __half* Xs   = symaddr<__half>(g_Xs);

    cudaFuncSetAttribute(mma_gemm, cudaFuncAttributeMaxDynamicSharedMemorySize, GEMM_SMEM);
    cudaFuncSetAttribute(mma_gemm_h<1>, cudaFuncAttributeMaxDynamicSharedMemorySize, H1_SMEM);
    cudaFuncSetAttribute(mma_gemm_h<2>, cudaFuncAttributeMaxDynamicSharedMemorySize, H2_SMEM);

    dim3 tb(32, 8);

    // input/weight conversions (one-time)
    tsplit2_kernel<<<dim3(LO/32, Nn/32, Bb), tb>>>(X, (long)Nn*LO, XtH, XtL, (long)LO*Nn, Nn, LO);
    castH_kernel<<<dim3(2048, Bb), 256>>>(X, (long)Nn*LO, Xs, (long)Nn*LO, Nn*LO/2);
    split2_kernel<<<dim3(512, 1), 256>>>(wq, 0, WqH, WqL, 0, LO*LO/2);
    split2_kernel<<<dim3(4096, 1), 256>>>(wk, 0, WkH, WkL, 0, HI*LO/2);
    tsplitH_kernel<<<dim3(LO/32, LO/32, 1), tb>>>(wv, WvTs, LO, LO);
    castH_kernel<<<dim3(8192, 1), 256>>>(ow, 0, Os, 0, HI*HI/2);

    // bias correction vectors (exact; zero-valued in this dataset)
    zero_kernel<<<(Bb*LO + 255)/256, 256>>>(s, Bb*LO);
    colsum_kernel<<<dim3(32, Bb), 512>>>(X, s);
    rowdot_kernel<<<dim3(LO/8, Bb), 256>>>(wq, s, u, LO, LO, nullptr);
    rowdot_kernel<<<dim3(HI/8, Bb), 256>>>(wk, s, v, HI, LO, nullptr);

    // -------- score chain (bf16x3) --------
    // G_b = Xt Xt^T   [512,512] K=2048  -> bf16 hi/lo split epilogue
    mma_gemm<<<dim3(LO/128, LO/128, Bb), 256, GEMM_SMEM>>>(
        Nn, XtH, XtL, (long)LO*Nn, XtH, XtL, (long)LO*Nn,
        nullptr, GH, GL, LO, (long)LO*LO);

    // T_b = Wq G_b
    mma_gemm<<<dim3(LO/128, LO/128, Bb), 256, GEMM_SMEM>>>(
        LO, WqH, WqL, 0, GH, GL, (long)LO*LO,
        nullptr, TH, TL, LO, (long)LO*LO);

    // E_b = T_b Wk^T  [512,4096] K=512  -> fp32
    mma_gemm<<<dim3(HI/128, LO/128, Bb), 256, GEMM_SMEM>>>(
        LO, TH, TL, (long)LO*LO, WkH, WkL, 0,
        E, nullptr, nullptr, HI, (long)LO*HI);

    // A_b = softmax(e) + softmax(minmaxnorm(e, mask)) -> single fp16
    attn_kernel<<<dim3(LO, Bb), 256>>>(E, lk, u, bq, v, bk, As);

    // bias path: w_b = bv^T A_b ; z_b = w_b O^T + o_b
    wvec_kernel<<<dim3(HI/256, Bb), 256>>>(As, bv, w);
    rowdot_kernel<<<dim3(HI/8, Bb), 256>>>(ow, w, z, HI, HI, ob);

    // -------- value chain (fp16) --------
    // S_b = O A_b^T   [4096,512] K=4096 (dominant, single x single) -> single
    mma_gemm_h<1><<<dim3(LO/128, HI/128, Bb), 256, H1_SMEM>>>(
        HI, Os, nullptr, 0, As, (long)LO*HI,
        nullptr, nullptr, nullptr, Ss, LO, (long)HI*LO, nullptr, 0);

    // Rt_b = S_b Wv   [4096,512] K=512 (single x single) -> single fp16
    mma_gemm_h<1><<<dim3(LO/128, HI/128, Bb), 256, H1_SMEM>>>(
        LO, Ss, nullptr, (long)HI*LO, WvTs, 0,
        nullptr, nullptr, nullptr, Rts, LO, (long)HI*LO, nullptr, 0);

    // out_b = X_b R_b + z_b  [2048,4096] K=512 (single x single)
    mma_gemm_h<1><<<dim3(HI/128, Nn/128, Bb), 256, H1_SMEM>>>(
        LO, Xs, nullptr, (long)Nn*LO, Rts, (long)HI*LO,
        out, nullptr, nullptr, nullptr, HI, (long)Nn*HI, z, HI);

    (void)in_sizes; (void)n_in; (void)out_size;
}